// round 1
// baseline (speedup 1.0000x reference)
#include <cuda_runtime.h>
#include <cuda_bf16.h>
#include <cstdint>

// ---------------- problem constants ----------------
#define B_    16
#define Hh    64
#define WRES  64
#define Cc    512
#define NHh   16
#define WHh   8
#define WWw   8
#define Nn    64          // tokens per window
#define HD    32          // head dim
#define HID   2048
#define NWIN  1024        // B * (H/WH) * (W/WW)
#define MROWS 65536       // NWIN * Nn == B * H * WRES
#define PI_F  3.14159265358979323846f

// ---------------- scratch (device globals; no allocation allowed) ----------------
__device__ float g_xw [MROWS * Cc];       // LN1 + window partition
__device__ float g_dw [MROWS];            // window-partitioned D
__device__ float g_qkv[MROWS * 3 * Cc];   // qkv
__device__ float g_ctx[MROWS * Cc];       // attention context (window layout)
__device__ float g_x2 [MROWS * Cc];       // after proj + residual (spatial layout)
__device__ float g_xn2[MROWS * Cc];       // LN2 output
__device__ float g_h  [MROWS * HID];      // fc1/gelu output
__device__ float g_aphi[NHh * Nn * Nn];   // azimuth bias table (h,i,j)

// ---------------- A_phi precompute ----------------
__global__ void aphi_kernel(const float* __restrict__ a_p, const float* __restrict__ b_p)
{
    int idx = blockIdx.x * blockDim.x + threadIdx.x;   // [0, 16*4096)
    if (idx >= NHh * Nn * Nn) return;
    int h   = idx >> 12;
    int rem = idx & 4095;
    int i   = rem >> 6, j = rem & 63;
    int xi = i & 7, xj = j & 7;
    int az = xi - xj;
    int ip = az < 0 ? az + 15 : az;
    float azf = (float)az * (2.0f * PI_F / (float)WRES);
    g_aphi[idx] = a_p[ip * NHh + h] * cosf(azf) + b_p[ip * NHh + h] * sinf(azf);
}

// ---------------- LayerNorm (optionally fused window partition) ----------------
template<bool PERM>
__launch_bounds__(128)
__global__ void ln_kernel(const float* __restrict__ x, const float* __restrict__ g,
                          const float* __restrict__ b, const float* __restrict__ D,
                          float* __restrict__ out, float* __restrict__ dwout)
{
    int r   = blockIdx.x;
    int tid = threadIdx.x;
    float4 v = ((const float4*)(x + (size_t)r * Cc))[tid];
    float s  = v.x + v.y + v.z + v.w;
    float sq = v.x * v.x + v.y * v.y + v.z * v.z + v.w * v.w;
    #pragma unroll
    for (int o = 16; o; o >>= 1) {
        s  += __shfl_xor_sync(0xffffffffu, s,  o);
        sq += __shfl_xor_sync(0xffffffffu, sq, o);
    }
    __shared__ float ss[4], sqs[4];
    int w = tid >> 5;
    if ((tid & 31) == 0) { ss[w] = s; sqs[w] = sq; }
    __syncthreads();
    s  = ss[0]  + ss[1]  + ss[2]  + ss[3];
    sq = sqs[0] + sqs[1] + sqs[2] + sqs[3];
    float mean = s * (1.0f / Cc);
    float var  = sq * (1.0f / Cc) - mean * mean;
    float rstd = rsqrtf(var + 1e-5f);
    float4 gg = ((const float4*)g)[tid];
    float4 bb = ((const float4*)b)[tid];
    float4 o;
    o.x = (v.x - mean) * rstd * gg.x + bb.x;
    o.y = (v.y - mean) * rstd * gg.y + bb.y;
    o.z = (v.z - mean) * rstd * gg.z + bb.z;
    o.w = (v.w - mean) * rstd * gg.w + bb.w;
    int dst = r;
    if (PERM) {
        int bI = r >> 12;             // batch
        int hh = (r >> 6) & 63;       // spatial row
        int wc = r & 63;              // spatial col
        int win = bI * 64 + (hh >> 3) * 8 + (wc >> 3);
        int rin = (hh & 7) * 8 + (wc & 7);
        dst = win * 64 + rin;
        if (tid == 0) dwout[dst] = D[r];
    }
    ((float4*)(out + (size_t)dst * Cc))[tid] = o;
}

// ---------------- generic SGEMM: Y = A(MxK) @ W^T (W is NoutxK) + bias ----------------
// MODE 0: plain              MODE 1: window-reverse + residual add
// MODE 2: exact GELU         MODE 3: residual add
template<int MODE>
__launch_bounds__(256)
__global__ void gemm_kernel(const float* __restrict__ A, const float* __restrict__ W,
                            const float* __restrict__ bias, const float* __restrict__ res,
                            float* __restrict__ out, int M, int N, int K)
{
    const int BM = 128, BN = 64, BK = 16;
    __shared__ float As[BK * BM];
    __shared__ float Ws[BK * BN];
    int bm = blockIdx.y * BM;
    int bn = blockIdx.x * BN;
    int tid = threadIdx.x;
    int tx = tid & 15;        // col group (x4)
    int ty = tid >> 4;        // row group (x8)

    float acc[8][4];
    #pragma unroll
    for (int i = 0; i < 8; i++)
        #pragma unroll
        for (int j = 0; j < 4; j++) acc[i][j] = 0.0f;

    for (int kt = 0; kt < K; kt += BK) {
        // load A tile (128x16) transposed into As[k][m]
        #pragma unroll
        for (int l = 0; l < 2; l++) {
            int s = tid + l * 256;
            int row = s >> 2;
            int kq  = (s & 3) * 4;
            float4 v = *(const float4*)(A + (size_t)(bm + row) * K + kt + kq);
            As[(kq + 0) * BM + row] = v.x;
            As[(kq + 1) * BM + row] = v.y;
            As[(kq + 2) * BM + row] = v.z;
            As[(kq + 3) * BM + row] = v.w;
        }
        // load W tile (64x16) transposed into Ws[k][n]
        {
            int s = tid;
            int row = s >> 2;
            int kq  = (s & 3) * 4;
            float4 v = *(const float4*)(W + (size_t)(bn + row) * K + kt + kq);
            Ws[(kq + 0) * BN + row] = v.x;
            Ws[(kq + 1) * BN + row] = v.y;
            Ws[(kq + 2) * BN + row] = v.z;
            Ws[(kq + 3) * BN + row] = v.w;
        }
        __syncthreads();
        #pragma unroll
        for (int k = 0; k < BK; k++) {
            float ra[8], rb[4];
            #pragma unroll
            for (int i = 0; i < 8; i++) ra[i] = As[k * BM + ty * 8 + i];
            #pragma unroll
            for (int j = 0; j < 4; j++) rb[j] = Ws[k * BN + tx * 4 + j];
            #pragma unroll
            for (int i = 0; i < 8; i++)
                #pragma unroll
                for (int j = 0; j < 4; j++) acc[i][j] += ra[i] * rb[j];
        }
        __syncthreads();
    }

    #pragma unroll
    for (int i = 0; i < 8; i++) {
        int m = bm + ty * 8 + i;
        size_t obase;
        if (MODE == 1) {
            int win = m >> 6, rin = m & 63;
            int bI = win >> 6, wb = (win >> 3) & 7, wwi = win & 7;
            int hh = wb * 8 + (rin >> 3);
            int wc = wwi * 8 + (rin & 7);
            int dst = bI * (Hh * WRES) + hh * 64 + wc;
            obase = (size_t)dst * N;
        } else {
            obase = (size_t)m * N;
        }
        #pragma unroll
        for (int j = 0; j < 4; j++) {
            int n = bn + tx * 4 + j;
            float v = acc[i][j] + bias[n];
            if (MODE == 0) {
                out[obase + n] = v;
            } else if (MODE == 1) {
                out[obase + n] = res[obase + n] + v;
            } else if (MODE == 2) {
                out[obase + n] = 0.5f * v * (1.0f + erff(v * 0.70710678118654752f));
            } else {
                out[obase + n] = res[obase + n] + v;
            }
        }
    }
}

// ---------------- fused attention per (window, head) ----------------
__launch_bounds__(128)
__global__ void attn_kernel(const float* __restrict__ qkv, const float* __restrict__ dw,
                            const float* __restrict__ aphi,
                            const float* __restrict__ a_r, const float* __restrict__ b_r,
                            float* __restrict__ ctx)
{
    __shared__ float qs[64 * 32];
    __shared__ float ks[64 * 33];
    __shared__ float vs[64 * 32];
    __shared__ float S [64 * 65];
    __shared__ float dws[64];
    __shared__ float ars[15 * 16];
    __shared__ float brs[15 * 16];

    int win = blockIdx.x >> 4;
    int h   = blockIdx.x & 15;
    int tid = threadIdx.x;
    int base = win * 64;
    const float scale = 0.17677669529663687f;   // 1/sqrt(32)

    for (int idx = tid; idx < 2048; idx += 128) {
        int i = idx >> 5, d = idx & 31;
        size_t rowoff = (size_t)(base + i) * (3 * Cc) + h * HD + d;
        qs[i * 32 + d] = qkv[rowoff] * scale;
        ks[i * 33 + d] = qkv[rowoff + Cc];
        vs[i * 32 + d] = qkv[rowoff + 2 * Cc];
    }
    if (tid < 64) dws[tid] = dw[base + tid];
    for (int t = tid; t < 240; t += 128) { ars[t] = a_r[t]; brs[t] = b_r[t]; }
    __syncthreads();

    const float cR = 2.0f * PI_F / 256.0f;      // 2*pi / R_MAX
    for (int idx = tid; idx < 4096; idx += 128) {
        int i = idx >> 6, j = idx & 63;
        float s = 0.0f;
        #pragma unroll
        for (int d = 0; d < 32; d++) s += qs[i * 32 + d] * ks[j * 33 + d];
        int rad = (i >> 3) - (j >> 3);
        int ir  = rad < 0 ? rad + 15 : rad;
        float ang = (float)rad * dws[j] * cR;
        float sn, cs;
        sincosf(ang, &sn, &cs);
        s += aphi[h * 4096 + idx] + ars[ir * 16 + h] * cs + brs[ir * 16 + h] * sn;
        S[i * 65 + j] = s;
    }
    __syncthreads();

    if (tid < 64) {
        float m = -1e30f;
        #pragma unroll 8
        for (int j = 0; j < 64; j++) m = fmaxf(m, S[tid * 65 + j]);
        float sum = 0.0f;
        #pragma unroll 8
        for (int j = 0; j < 64; j++) {
            float e = expf(S[tid * 65 + j] - m);
            S[tid * 65 + j] = e;
            sum += e;
        }
        float inv = 1.0f / sum;
        #pragma unroll 8
        for (int j = 0; j < 64; j++) S[tid * 65 + j] *= inv;
    }
    __syncthreads();

    for (int idx = tid; idx < 2048; idx += 128) {
        int i = idx >> 5, d = idx & 31;
        float s = 0.0f;
        #pragma unroll
        for (int j = 0; j < 64; j++) s += S[i * 65 + j] * vs[j * 32 + d];
        ctx[(size_t)(base + i) * Cc + h * HD + d] = s;
    }
}

// ---------------- launch ----------------
extern "C" void kernel_launch(void* const* d_in, const int* in_sizes, int n_in,
                              void* d_out, int out_size)
{
    const float* x       = (const float*)d_in[0];
    const float* D       = (const float*)d_in[1];
    const float* norm1_g = (const float*)d_in[2];
    const float* norm1_b = (const float*)d_in[3];
    const float* qkv_w   = (const float*)d_in[4];
    const float* qkv_b   = (const float*)d_in[5];
    const float* proj_w  = (const float*)d_in[6];
    const float* proj_b  = (const float*)d_in[7];
    const float* a_p     = (const float*)d_in[8];
    const float* b_p     = (const float*)d_in[9];
    const float* a_r     = (const float*)d_in[10];
    const float* b_r     = (const float*)d_in[11];
    const float* norm2_g = (const float*)d_in[12];
    const float* norm2_b = (const float*)d_in[13];
    const float* fc1_w   = (const float*)d_in[14];
    const float* fc1_b   = (const float*)d_in[15];
    const float* fc2_w   = (const float*)d_in[16];
    const float* fc2_b   = (const float*)d_in[17];
    float* out = (float*)d_out;

    float *p_xw, *p_dw, *p_qkv, *p_ctx, *p_x2, *p_xn2, *p_h, *p_aphi;
    cudaGetSymbolAddress((void**)&p_xw,   g_xw);
    cudaGetSymbolAddress((void**)&p_dw,   g_dw);
    cudaGetSymbolAddress((void**)&p_qkv,  g_qkv);
    cudaGetSymbolAddress((void**)&p_ctx,  g_ctx);
    cudaGetSymbolAddress((void**)&p_x2,   g_x2);
    cudaGetSymbolAddress((void**)&p_xn2,  g_xn2);
    cudaGetSymbolAddress((void**)&p_h,    g_h);
    cudaGetSymbolAddress((void**)&p_aphi, g_aphi);

    // 1. azimuth bias table
    aphi_kernel<<<(NHh * Nn * Nn + 255) / 256, 256>>>(a_p, b_p);

    // 2. LN1 + window partition (+ D partition)
    ln_kernel<true><<<MROWS, 128>>>(x, norm1_g, norm1_b, D, p_xw, p_dw);

    // 3. QKV GEMM: (65536 x 512) @ (512 x 1536)
    gemm_kernel<0><<<dim3(3 * Cc / 64, MROWS / 128), 256>>>(
        p_xw, qkv_w, qkv_b, nullptr, p_qkv, MROWS, 3 * Cc, Cc);

    // 4. attention per (window, head)
    attn_kernel<<<NWIN * NHh, 128>>>(p_qkv, p_dw, p_aphi, a_r, b_r, p_ctx);

    // 5. proj GEMM + window reverse + residual
    gemm_kernel<1><<<dim3(Cc / 64, MROWS / 128), 256>>>(
        p_ctx, proj_w, proj_b, x, p_x2, MROWS, Cc, Cc);

    // 6. LN2
    ln_kernel<false><<<MROWS, 128>>>(p_x2, norm2_g, norm2_b, nullptr, p_xn2, nullptr);

    // 7. fc1 + exact GELU
    gemm_kernel<2><<<dim3(HID / 64, MROWS / 128), 256>>>(
        p_xn2, fc1_w, fc1_b, nullptr, p_h, MROWS, HID, Cc);

    // 8. fc2 + residual -> out
    gemm_kernel<3><<<dim3(Cc / 64, MROWS / 128), 256>>>(
        p_h, fc2_w, fc2_b, p_x2, out, MROWS, Cc, HID);
}

// round 3
// speedup vs baseline: 4.0132x; 4.0132x over previous
#include <cuda_runtime.h>
#include <cuda_bf16.h>
#include <cstdint>

// ---------------- problem constants ----------------
#define B_    16
#define Hh    64
#define WRES  64
#define Cc    512
#define NHh   16
#define Nn    64
#define HD    32
#define HID   2048
#define NWIN  1024
#define MROWS 65536
#define PI_F  3.14159265358979323846f

// ---------------- scratch ----------------
__device__ float g_xw [MROWS * Cc];
__device__ float g_dw [MROWS];
__device__ float g_qkv[MROWS * 3 * Cc];
__device__ float g_ctx[MROWS * Cc];
__device__ float g_x2 [MROWS * Cc];
__device__ float g_xn2[MROWS * Cc];
__device__ float g_h  [MROWS * HID];
__device__ float g_aphi[NHh * Nn * Nn];

// ---------------- helpers ----------------
__device__ __forceinline__ uint32_t smem_u32(const void* p) {
    uint32_t a;
    asm("{ .reg .u64 t; cvta.to.shared.u64 t, %1; cvt.u32.u64 %0, t; }" : "=r"(a) : "l"(p));
    return a;
}
__device__ __forceinline__ void cp_async16(uint32_t saddr, const void* gaddr) {
    asm volatile("cp.async.cg.shared.global [%0], [%1], 16;" :: "r"(saddr), "l"(gaddr) : "memory");
}
__device__ __forceinline__ void cp_commit() {
    asm volatile("cp.async.commit_group;" ::: "memory");
}
template<int NN>
__device__ __forceinline__ void cp_wait() {
    asm volatile("cp.async.wait_group %0;" :: "n"(NN) : "memory");
}
__device__ __forceinline__ void ldmatrix4(uint32_t* r, uint32_t addr) {
    asm volatile("ldmatrix.sync.aligned.m8n8.x4.shared.b16 {%0,%1,%2,%3}, [%4];"
        : "=r"(r[0]), "=r"(r[1]), "=r"(r[2]), "=r"(r[3]) : "r"(addr));
}
__device__ __forceinline__ void mma_tf32(float* c, const uint32_t* a, const uint32_t* b) {
    asm volatile(
        "mma.sync.aligned.m16n8k8.row.col.f32.tf32.tf32.f32 "
        "{%0,%1,%2,%3}, {%4,%5,%6,%7}, {%8,%9}, {%0,%1,%2,%3};"
        : "+f"(c[0]), "+f"(c[1]), "+f"(c[2]), "+f"(c[3])
        : "r"(a[0]), "r"(a[1]), "r"(a[2]), "r"(a[3]), "r"(b[0]), "r"(b[1]));
}

// ---------------- A_phi precompute ----------------
__global__ void aphi_kernel(const float* __restrict__ a_p, const float* __restrict__ b_p)
{
    int idx = blockIdx.x * blockDim.x + threadIdx.x;
    if (idx >= NHh * Nn * Nn) return;
    int h = idx >> 12;
    int rem = idx & 4095;
    int i = rem >> 6, j = rem & 63;
    int az = (i & 7) - (j & 7);
    int ip = az < 0 ? az + 15 : az;
    float azf = (float)az * (2.0f * PI_F / (float)WRES);
    g_aphi[idx] = a_p[ip * NHh + h] * cosf(azf) + b_p[ip * NHh + h] * sinf(azf);
}

// ---------------- LayerNorm (+ optional window partition) ----------------
template<bool PERM>
__launch_bounds__(128)
__global__ void ln_kernel(const float* __restrict__ x, const float* __restrict__ g,
                          const float* __restrict__ b, const float* __restrict__ D,
                          float* __restrict__ out, float* __restrict__ dwout)
{
    int r = blockIdx.x;
    int tid = threadIdx.x;
    float4 v = ((const float4*)(x + (size_t)r * Cc))[tid];
    float s = v.x + v.y + v.z + v.w;
    float sq = v.x * v.x + v.y * v.y + v.z * v.z + v.w * v.w;
    #pragma unroll
    for (int o = 16; o; o >>= 1) {
        s += __shfl_xor_sync(0xffffffffu, s, o);
        sq += __shfl_xor_sync(0xffffffffu, sq, o);
    }
    __shared__ float ss[4], sqs[4];
    int w = tid >> 5;
    if ((tid & 31) == 0) { ss[w] = s; sqs[w] = sq; }
    __syncthreads();
    s = ss[0] + ss[1] + ss[2] + ss[3];
    sq = sqs[0] + sqs[1] + sqs[2] + sqs[3];
    float mean = s * (1.0f / Cc);
    float var = sq * (1.0f / Cc) - mean * mean;
    float rstd = rsqrtf(var + 1e-5f);
    float4 gg = ((const float4*)g)[tid];
    float4 bb = ((const float4*)b)[tid];
    float4 o;
    o.x = (v.x - mean) * rstd * gg.x + bb.x;
    o.y = (v.y - mean) * rstd * gg.y + bb.y;
    o.z = (v.z - mean) * rstd * gg.z + bb.z;
    o.w = (v.w - mean) * rstd * gg.w + bb.w;
    int dst = r;
    if (PERM) {
        int bI = r >> 12;
        int hh = (r >> 6) & 63;
        int wc = r & 63;
        int win = bI * 64 + (hh >> 3) * 8 + (wc >> 3);
        int rin = (hh & 7) * 8 + (wc & 7);
        dst = win * 64 + rin;
        if (tid == 0) dwout[dst] = D[r];
    }
    ((float4*)(out + (size_t)dst * Cc))[tid] = o;
}

// ============ tf32 mma.sync GEMM: Y = A(MxK) @ W^T (W NoutxK) + bias ============
// MODE 0: plain   MODE 1: window-reverse + residual   MODE 2: GELU   MODE 3: residual
// Tile BM=128, BN=128, BK=32. 2-stage cp.async pipeline. 8 warps, warp tile 64x32.
template<int MODE>
__launch_bounds__(256)
__global__ void gemm_mma(const float* __restrict__ A, const float* __restrict__ W,
                         const float* __restrict__ bias, const float* __restrict__ res,
                         float* __restrict__ out, int M, int N, int K)
{
    extern __shared__ char smem[];
    const uint32_t sbase = smem_u32(smem);   // stage s: A at s*32768, B at +16384
    const int tid = threadIdx.x;
    const int bm = blockIdx.y * 128;
    const int bn = blockIdx.x * 128;
    const int warp = tid >> 5, lane = tid & 31;
    const int wm = warp & 1;      // 2 warps over M (64 rows each)
    const int wn = warp >> 1;     // 4 warps over N (32 cols each)

    float acc[4][4][4];
    #pragma unroll
    for (int i = 0; i < 4; i++)
        #pragma unroll
        for (int j = 0; j < 4; j++)
            #pragma unroll
            for (int q = 0; q < 4; q++) acc[i][j][q] = 0.0f;

    const int ldrow = tid >> 3;         // 0..31 handled via idx loop
    const int ldseg = tid & 7;
    (void)ldrow; (void)ldseg;

    const int nk = K >> 5;

    // prefetch helper (macro-ish lambda)
    auto prefetch = [&](int kt, int stage) {
        uint32_t ab = sbase + (uint32_t)stage * 32768u;
        uint32_t bb = ab + 16384u;
        const float* Ap = A + (size_t)bm * K + (size_t)kt * 32;
        const float* Wp = W + (size_t)bn * K + (size_t)kt * 32;
        #pragma unroll
        for (int t = 0; t < 4; t++) {
            int idx = tid + t * 256;
            int row = idx >> 3, seg = idx & 7;
            uint32_t so = (uint32_t)(row * 128 + ((seg ^ (row & 7)) << 4));
            cp_async16(ab + so, Ap + (size_t)row * K + seg * 4);
            cp_async16(bb + so, Wp + (size_t)row * K + seg * 4);
        }
    };

    prefetch(0, 0);
    cp_commit();

    for (int kt = 0; kt < nk; kt++) {
        if (kt + 1 < nk) {
            prefetch(kt + 1, (kt + 1) & 1);
            cp_commit();
            cp_wait<1>();
        } else {
            cp_wait<0>();
        }
        __syncthreads();

        uint32_t ab = sbase + (uint32_t)(kt & 1) * 32768u;
        uint32_t bb = ab + 16384u;

        #pragma unroll
        for (int ks = 0; ks < 4; ks++) {
            uint32_t af[4][4];
            uint32_t bf[4][2];
            #pragma unroll
            for (int am = 0; am < 4; am++) {
                int row = wm * 64 + am * 16 + ((lane >> 3) & 1) * 8 + (lane & 7);
                int koff = ks * 32 + (lane >> 4) * 16;
                uint32_t addr = ab + (uint32_t)(row * 128 + (koff ^ ((row & 7) << 4)));
                ldmatrix4(af[am], addr);
            }
            #pragma unroll
            for (int bp = 0; bp < 2; bp++) {
                int nrow = wn * 32 + bp * 16 + ((lane >> 4) & 1) * 8 + (lane & 7);
                int koff = ks * 32 + ((lane >> 3) & 1) * 16;
                uint32_t addr = bb + (uint32_t)(nrow * 128 + (koff ^ ((nrow & 7) << 4)));
                uint32_t r[4];
                ldmatrix4(r, addr);
                bf[bp * 2 + 0][0] = r[0]; bf[bp * 2 + 0][1] = r[1];
                bf[bp * 2 + 1][0] = r[2]; bf[bp * 2 + 1][1] = r[3];
            }
            #pragma unroll
            for (int am = 0; am < 4; am++)
                #pragma unroll
                for (int an = 0; an < 4; an++)
                    mma_tf32(acc[am][an], af[am], bf[an]);
        }
        __syncthreads();
    }

    // ---------------- epilogue ----------------
    #pragma unroll
    for (int am = 0; am < 4; am++) {
        #pragma unroll
        for (int half = 0; half < 2; half++) {
            int m = bm + wm * 64 + am * 16 + half * 8 + (lane >> 2);
            size_t obase;
            if (MODE == 1) {
                int win = m >> 6, rin = m & 63;
                int bI = win >> 6, wb = (win >> 3) & 7, wwi = win & 7;
                int hh = wb * 8 + (rin >> 3);
                int wc = wwi * 8 + (rin & 7);
                obase = (size_t)(bI * (Hh * WRES) + hh * 64 + wc) * N;
            } else {
                obase = (size_t)m * N;
            }
            #pragma unroll
            for (int an = 0; an < 4; an++) {
                int n = bn + wn * 32 + an * 8 + (lane & 3) * 2;
                float2 bv = *(const float2*)(bias + n);
                float x0 = acc[am][an][half * 2 + 0] + bv.x;
                float x1 = acc[am][an][half * 2 + 1] + bv.y;
                if (MODE == 2) {
                    x0 = 0.5f * x0 * (1.0f + erff(x0 * 0.70710678118654752f));
                    x1 = 0.5f * x1 * (1.0f + erff(x1 * 0.70710678118654752f));
                }
                if (MODE == 1 || MODE == 3) {
                    float2 rv = *(const float2*)(res + obase + n);
                    x0 += rv.x; x1 += rv.y;
                }
                float2 o; o.x = x0; o.y = x1;
                *(float2*)(out + obase + n) = o;
            }
        }
    }
}

// ---------------- fused attention per (window, head) ----------------
__launch_bounds__(128)
__global__ void attn_kernel(const float* __restrict__ qkv, const float* __restrict__ dw,
                            const float* __restrict__ aphi,
                            const float* __restrict__ a_r, const float* __restrict__ b_r,
                            float* __restrict__ ctx)
{
    __shared__ float qs[64 * 32];
    __shared__ float ks[64 * 33];
    __shared__ float vs[64 * 32];
    __shared__ float S [64 * 65];
    __shared__ float dws[64];
    __shared__ float ars[15 * 16];
    __shared__ float brs[15 * 16];

    int win = blockIdx.x >> 4;
    int h = blockIdx.x & 15;
    int tid = threadIdx.x;
    int base = win * 64;
    const float scale = 0.17677669529663687f;

    for (int idx = tid; idx < 2048; idx += 128) {
        int i = idx >> 5, d = idx & 31;
        size_t rowoff = (size_t)(base + i) * (3 * Cc) + h * HD + d;
        qs[i * 32 + d] = qkv[rowoff] * scale;
        ks[i * 33 + d] = qkv[rowoff + Cc];
        vs[i * 32 + d] = qkv[rowoff + 2 * Cc];
    }
    if (tid < 64) dws[tid] = dw[base + tid];
    for (int t = tid; t < 240; t += 128) { ars[t] = a_r[t]; brs[t] = b_r[t]; }
    __syncthreads();

    const float cR = 2.0f * PI_F / 256.0f;
    for (int idx = tid; idx < 4096; idx += 128) {
        int i = idx >> 6, j = idx & 63;
        float s = 0.0f;
        #pragma unroll
        for (int d = 0; d < 32; d++) s += qs[i * 32 + d] * ks[j * 33 + d];
        int rad = (i >> 3) - (j >> 3);
        int ir = rad < 0 ? rad + 15 : rad;
        float ang = (float)rad * dws[j] * cR;
        float sn, cs;
        sincosf(ang, &sn, &cs);
        s += aphi[h * 4096 + idx] + ars[ir * 16 + h] * cs + brs[ir * 16 + h] * sn;
        S[i * 65 + j] = s;
    }
    __syncthreads();

    if (tid < 64) {
        float m = -1e30f;
        #pragma unroll 8
        for (int j = 0; j < 64; j++) m = fmaxf(m, S[tid * 65 + j]);
        float sum = 0.0f;
        #pragma unroll 8
        for (int j = 0; j < 64; j++) {
            float e = expf(S[tid * 65 + j] - m);
            S[tid * 65 + j] = e;
            sum += e;
        }
        float inv = 1.0f / sum;
        #pragma unroll 8
        for (int j = 0; j < 64; j++) S[tid * 65 + j] *= inv;
    }
    __syncthreads();

    for (int idx = tid; idx < 2048; idx += 128) {
        int i = idx >> 5, d = idx & 31;
        float s = 0.0f;
        #pragma unroll
        for (int j = 0; j < 64; j++) s += S[i * 65 + j] * vs[j * 32 + d];
        ctx[(size_t)(base + i) * Cc + h * HD + d] = s;
    }
}

// ---------------- launch ----------------
#define GEMM_SMEM 65536

extern "C" void kernel_launch(void* const* d_in, const int* in_sizes, int n_in,
                              void* d_out, int out_size)
{
    const float* x       = (const float*)d_in[0];
    const float* D       = (const float*)d_in[1];
    const float* norm1_g = (const float*)d_in[2];
    const float* norm1_b = (const float*)d_in[3];
    const float* qkv_w   = (const float*)d_in[4];
    const float* qkv_b   = (const float*)d_in[5];
    const float* proj_w  = (const float*)d_in[6];
    const float* proj_b  = (const float*)d_in[7];
    const float* a_p     = (const float*)d_in[8];
    const float* b_p     = (const float*)d_in[9];
    const float* a_r     = (const float*)d_in[10];
    const float* b_r     = (const float*)d_in[11];
    const float* norm2_g = (const float*)d_in[12];
    const float* norm2_b = (const float*)d_in[13];
    const float* fc1_w   = (const float*)d_in[14];
    const float* fc1_b   = (const float*)d_in[15];
    const float* fc2_w   = (const float*)d_in[16];
    const float* fc2_b   = (const float*)d_in[17];
    float* out = (float*)d_out;

    float *p_xw, *p_dw, *p_qkv, *p_ctx, *p_x2, *p_xn2, *p_h, *p_aphi;
    cudaGetSymbolAddress((void**)&p_xw,   g_xw);
    cudaGetSymbolAddress((void**)&p_dw,   g_dw);
    cudaGetSymbolAddress((void**)&p_qkv,  g_qkv);
    cudaGetSymbolAddress((void**)&p_ctx,  g_ctx);
    cudaGetSymbolAddress((void**)&p_x2,   g_x2);
    cudaGetSymbolAddress((void**)&p_xn2,  g_xn2);
    cudaGetSymbolAddress((void**)&p_h,    g_h);
    cudaGetSymbolAddress((void**)&p_aphi, g_aphi);

    cudaFuncSetAttribute(gemm_mma<0>, cudaFuncAttributeMaxDynamicSharedMemorySize, GEMM_SMEM);
    cudaFuncSetAttribute(gemm_mma<1>, cudaFuncAttributeMaxDynamicSharedMemorySize, GEMM_SMEM);
    cudaFuncSetAttribute(gemm_mma<2>, cudaFuncAttributeMaxDynamicSharedMemorySize, GEMM_SMEM);
    cudaFuncSetAttribute(gemm_mma<3>, cudaFuncAttributeMaxDynamicSharedMemorySize, GEMM_SMEM);

    // 1. azimuth bias table
    aphi_kernel<<<(NHh * Nn * Nn + 255) / 256, 256>>>(a_p, b_p);

    // 2. LN1 + window partition
    ln_kernel<true><<<MROWS, 128>>>(x, norm1_g, norm1_b, D, p_xw, p_dw);

    // 3. QKV GEMM (65536 x 512) @ (512 x 1536)
    gemm_mma<0><<<dim3(3 * Cc / 128, MROWS / 128), 256, GEMM_SMEM>>>(
        p_xw, qkv_w, qkv_b, nullptr, p_qkv, MROWS, 3 * Cc, Cc);

    // 4. attention
    attn_kernel<<<NWIN * NHh, 128>>>(p_qkv, p_dw, p_aphi, a_r, b_r, p_ctx);

    // 5. proj GEMM + window reverse + residual
    gemm_mma<1><<<dim3(Cc / 128, MROWS / 128), 256, GEMM_SMEM>>>(
        p_ctx, proj_w, proj_b, x, p_x2, MROWS, Cc, Cc);

    // 6. LN2
    ln_kernel<false><<<MROWS, 128>>>(p_x2, norm2_g, norm2_b, nullptr, p_xn2, nullptr);

    // 7. fc1 + GELU
    gemm_mma<2><<<dim3(HID / 128, MROWS / 128), 256, GEMM_SMEM>>>(
        p_xn2, fc1_w, fc1_b, nullptr, p_h, MROWS, HID, Cc);

    // 8. fc2 + residual -> out
    gemm_mma<3><<<dim3(Cc / 128, MROWS / 128), 256, GEMM_SMEM>>>(
        p_h, fc2_w, fc2_b, p_x2, out, MROWS, Cc, HID);
}

// round 4
// speedup vs baseline: 4.2234x; 1.0524x over previous
#include <cuda_runtime.h>
#include <cuda_bf16.h>
#include <cstdint>

// ---------------- problem constants ----------------
#define B_    16
#define Hh    64
#define WRES  64
#define Cc    512
#define NHh   16
#define Nn    64
#define HD    32
#define HID   2048
#define NWIN  1024
#define MROWS 65536
#define PI_F  3.14159265358979323846f

// ---------------- scratch ----------------
__device__ float g_xw [MROWS * Cc];
__device__ float g_dw [MROWS];
__device__ float g_qkv[MROWS * 3 * Cc];
__device__ float g_ctx[MROWS * Cc];
__device__ float g_x2 [MROWS * Cc];
__device__ float g_xn2[MROWS * Cc];
__device__ float g_h  [MROWS * HID];
__device__ float g_aphi[NHh * Nn * Nn];
__device__ float g_cst[NWIN * 15 * 64];
__device__ float g_snt[NWIN * 15 * 64];

// ---------------- helpers ----------------
__device__ __forceinline__ uint32_t smem_u32(const void* p) {
    uint32_t a;
    asm("{ .reg .u64 t; cvta.to.shared.u64 t, %1; cvt.u32.u64 %0, t; }" : "=r"(a) : "l"(p));
    return a;
}
__device__ __forceinline__ void cp_async16(uint32_t saddr, const void* gaddr) {
    asm volatile("cp.async.cg.shared.global [%0], [%1], 16;" :: "r"(saddr), "l"(gaddr) : "memory");
}
__device__ __forceinline__ void cp_commit() {
    asm volatile("cp.async.commit_group;" ::: "memory");
}
template<int NN>
__device__ __forceinline__ void cp_wait() {
    asm volatile("cp.async.wait_group %0;" :: "n"(NN) : "memory");
}
__device__ __forceinline__ void ldmatrix4(uint32_t* r, uint32_t addr) {
    asm volatile("ldmatrix.sync.aligned.m8n8.x4.shared.b16 {%0,%1,%2,%3}, [%4];"
        : "=r"(r[0]), "=r"(r[1]), "=r"(r[2]), "=r"(r[3]) : "r"(addr));
}
__device__ __forceinline__ void mma_tf32(float* c, const uint32_t* a, const uint32_t* b) {
    asm volatile(
        "mma.sync.aligned.m16n8k8.row.col.f32.tf32.tf32.f32 "
        "{%0,%1,%2,%3}, {%4,%5,%6,%7}, {%8,%9}, {%0,%1,%2,%3};"
        : "+f"(c[0]), "+f"(c[1]), "+f"(c[2]), "+f"(c[3])
        : "r"(a[0]), "r"(a[1]), "r"(a[2]), "r"(a[3]), "r"(b[0]), "r"(b[1]));
}
__device__ __forceinline__ void mma_tf32_f(float* c, const float* a, float b0, float b1) {
    asm volatile(
        "mma.sync.aligned.m16n8k8.row.col.f32.tf32.tf32.f32 "
        "{%0,%1,%2,%3}, {%4,%5,%6,%7}, {%8,%9}, {%0,%1,%2,%3};"
        : "+f"(c[0]), "+f"(c[1]), "+f"(c[2]), "+f"(c[3])
        : "r"(__float_as_uint(a[0])), "r"(__float_as_uint(a[1])),
          "r"(__float_as_uint(a[2])), "r"(__float_as_uint(a[3])),
          "r"(__float_as_uint(b0)), "r"(__float_as_uint(b1)));
}

// ---------------- A_phi precompute ----------------
__global__ void aphi_kernel(const float* __restrict__ a_p, const float* __restrict__ b_p)
{
    int idx = blockIdx.x * blockDim.x + threadIdx.x;
    if (idx >= NHh * Nn * Nn) return;
    int h = idx >> 12;
    int rem = idx & 4095;
    int i = rem >> 6, j = rem & 63;
    int az = (i & 7) - (j & 7);
    int ip = az < 0 ? az + 15 : az;
    float azf = (float)az * (2.0f * PI_F / (float)WRES);
    g_aphi[idx] = a_p[ip * NHh + h] * cosf(azf) + b_p[ip * NHh + h] * sinf(azf);
}

// ---------------- radial sincos tables: [win][rad+7][j] ----------------
__global__ void rtab_kernel(const float* __restrict__ dw)
{
    int idx = blockIdx.x * blockDim.x + threadIdx.x;
    if (idx >= NWIN * 15 * 64) return;
    int win = idx / 960;
    int rem = idx - win * 960;
    int ir = rem >> 6;           // 0..14, rad = ir-7
    int j = rem & 63;
    float ang = (float)(ir - 7) * dw[win * 64 + j] * (2.0f * PI_F / 256.0f);
    float sn, cs;
    sincosf(ang, &sn, &cs);
    g_cst[idx] = cs;
    g_snt[idx] = sn;
}

// ---------------- LayerNorm (+ optional window partition) ----------------
template<bool PERM>
__launch_bounds__(128)
__global__ void ln_kernel(const float* __restrict__ x, const float* __restrict__ g,
                          const float* __restrict__ b, const float* __restrict__ D,
                          float* __restrict__ out, float* __restrict__ dwout)
{
    int r = blockIdx.x;
    int tid = threadIdx.x;
    float4 v = ((const float4*)(x + (size_t)r * Cc))[tid];
    float s = v.x + v.y + v.z + v.w;
    float sq = v.x * v.x + v.y * v.y + v.z * v.z + v.w * v.w;
    #pragma unroll
    for (int o = 16; o; o >>= 1) {
        s += __shfl_xor_sync(0xffffffffu, s, o);
        sq += __shfl_xor_sync(0xffffffffu, sq, o);
    }
    __shared__ float ss[4], sqs[4];
    int w = tid >> 5;
    if ((tid & 31) == 0) { ss[w] = s; sqs[w] = sq; }
    __syncthreads();
    s = ss[0] + ss[1] + ss[2] + ss[3];
    sq = sqs[0] + sqs[1] + sqs[2] + sqs[3];
    float mean = s * (1.0f / Cc);
    float var = sq * (1.0f / Cc) - mean * mean;
    float rstd = rsqrtf(var + 1e-5f);
    float4 gg = ((const float4*)g)[tid];
    float4 bb = ((const float4*)b)[tid];
    float4 o;
    o.x = (v.x - mean) * rstd * gg.x + bb.x;
    o.y = (v.y - mean) * rstd * gg.y + bb.y;
    o.z = (v.z - mean) * rstd * gg.z + bb.z;
    o.w = (v.w - mean) * rstd * gg.w + bb.w;
    int dst = r;
    if (PERM) {
        int bI = r >> 12;
        int hh = (r >> 6) & 63;
        int wc = r & 63;
        int win = bI * 64 + (hh >> 3) * 8 + (wc >> 3);
        int rin = (hh & 7) * 8 + (wc & 7);
        dst = win * 64 + rin;
        if (tid == 0) dwout[dst] = D[r];
    }
    ((float4*)(out + (size_t)dst * Cc))[tid] = o;
}

// ============ tf32 mma.sync GEMM: Y = A(MxK) @ W^T (W NoutxK) + bias ============
// Tile BM=128, BN=256, BK=32. 3-stage cp.async pipeline, one barrier/iter.
// 8 warps, warp tile 64x64.
// MODE 0: plain   MODE 1: window-reverse + residual   MODE 2: GELU   MODE 3: residual
#define GSTAGE 49152
template<int MODE>
__launch_bounds__(256, 1)
__global__ void gemm_mma(const float* __restrict__ A, const float* __restrict__ W,
                         const float* __restrict__ bias, const float* __restrict__ res,
                         float* __restrict__ out, int M, int N, int K)
{
    extern __shared__ char smem[];
    const uint32_t sbase = smem_u32(smem);   // stage s: A (16KB) then B (32KB)
    const int tid = threadIdx.x;
    const int bm = blockIdx.y * 128;
    const int bn = blockIdx.x * 256;
    const int warp = tid >> 5, lane = tid & 31;
    const int wm = warp & 1;      // 2 warps over M (64 rows each)
    const int wn = warp >> 1;     // 4 warps over N (64 cols each)

    float acc[4][8][4];
    #pragma unroll
    for (int i = 0; i < 4; i++)
        #pragma unroll
        for (int j = 0; j < 8; j++)
            #pragma unroll
            for (int q = 0; q < 4; q++) acc[i][j][q] = 0.0f;

    const int nk = K >> 5;

    auto prefetch = [&](int kt, int stage) {
        uint32_t ab = sbase + (uint32_t)stage * GSTAGE;
        uint32_t bb = ab + 16384u;
        const float* Ap = A + (size_t)bm * K + (size_t)kt * 32;
        const float* Wp = W + (size_t)bn * K + (size_t)kt * 32;
        #pragma unroll
        for (int t = 0; t < 4; t++) {
            int idx = tid + t * 256;
            int row = idx >> 3, seg = idx & 7;
            uint32_t so = (uint32_t)(row * 128 + ((seg ^ (row & 7)) << 4));
            cp_async16(ab + so, Ap + (size_t)row * K + seg * 4);
        }
        #pragma unroll
        for (int t = 0; t < 8; t++) {
            int idx = tid + t * 256;
            int row = idx >> 3, seg = idx & 7;
            uint32_t so = (uint32_t)(row * 128 + ((seg ^ (row & 7)) << 4));
            cp_async16(bb + so, Wp + (size_t)row * K + seg * 4);
        }
    };

    prefetch(0, 0); cp_commit();
    prefetch(1, 1); cp_commit();

    for (int kt = 0; kt < nk; kt++) {
        cp_wait<1>();
        __syncthreads();
        if (kt + 2 < nk) {
            int st = (kt + 2) % 3;
            prefetch(kt + 2, st);
        }
        cp_commit();

        uint32_t ab = sbase + (uint32_t)(kt % 3) * GSTAGE;
        uint32_t bb = ab + 16384u;

        #pragma unroll
        for (int ks = 0; ks < 4; ks++) {
            uint32_t af[4][4];
            uint32_t bf[8][2];
            #pragma unroll
            for (int am = 0; am < 4; am++) {
                int row = wm * 64 + am * 16 + ((lane >> 3) & 1) * 8 + (lane & 7);
                int koff = ks * 32 + (lane >> 4) * 16;
                uint32_t addr = ab + (uint32_t)(row * 128 + (koff ^ ((row & 7) << 4)));
                ldmatrix4(af[am], addr);
            }
            #pragma unroll
            for (int bp = 0; bp < 4; bp++) {
                int nrow = wn * 64 + bp * 16 + ((lane >> 4) & 1) * 8 + (lane & 7);
                int koff = ks * 32 + ((lane >> 3) & 1) * 16;
                uint32_t addr = bb + (uint32_t)(nrow * 128 + (koff ^ ((nrow & 7) << 4)));
                uint32_t r[4];
                ldmatrix4(r, addr);
                bf[bp * 2 + 0][0] = r[0]; bf[bp * 2 + 0][1] = r[1];
                bf[bp * 2 + 1][0] = r[2]; bf[bp * 2 + 1][1] = r[3];
            }
            #pragma unroll
            for (int am = 0; am < 4; am++)
                #pragma unroll
                for (int an = 0; an < 8; an++)
                    mma_tf32(acc[am][an], af[am], bf[an]);
        }
    }

    // ---------------- epilogue ----------------
    #pragma unroll
    for (int am = 0; am < 4; am++) {
        #pragma unroll
        for (int half = 0; half < 2; half++) {
            int m = bm + wm * 64 + am * 16 + half * 8 + (lane >> 2);
            size_t obase;
            if (MODE == 1) {
                int win = m >> 6, rin = m & 63;
                int bI = win >> 6, wb = (win >> 3) & 7, wwi = win & 7;
                int hh = wb * 8 + (rin >> 3);
                int wc = wwi * 8 + (rin & 7);
                obase = (size_t)(bI * (Hh * WRES) + hh * 64 + wc) * N;
            } else {
                obase = (size_t)m * N;
            }
            #pragma unroll
            for (int an = 0; an < 8; an++) {
                int n = bn + wn * 64 + an * 8 + (lane & 3) * 2;
                float2 bv = *(const float2*)(bias + n);
                float x0 = acc[am][an][half * 2 + 0] + bv.x;
                float x1 = acc[am][an][half * 2 + 1] + bv.y;
                if (MODE == 2) {
                    x0 = 0.5f * x0 * (1.0f + erff(x0 * 0.70710678118654752f));
                    x1 = 0.5f * x1 * (1.0f + erff(x1 * 0.70710678118654752f));
                }
                if (MODE == 1 || MODE == 3) {
                    float2 rv = *(const float2*)(res + obase + n);
                    x0 += rv.x; x1 += rv.y;
                }
                float2 o; o.x = x0; o.y = x1;
                *(float2*)(out + obase + n) = o;
            }
        }
    }
}

// ============ tensor-core attention per (window, head) ============
// 128 threads, 4 warps; warp w owns S rows [w*16, w*16+16).
// SMEM float offsets:
#define A_QS 0
#define A_KS 2304
#define A_VS 4608
#define A_SS 6912      /* 64 x 68 */
#define A_AP 11264     /* 4096 */
#define A_CT 15360     /* 960 */
#define A_ST 16320     /* 960 */
#define A_AR 17280     /* 16 */
#define A_BR 17296     /* 16 */
#define ATTN_SMEM (17312 * 4)

__launch_bounds__(128)
__global__ void attn_mma(const float* __restrict__ qkv,
                         const float* __restrict__ aphi,
                         const float* __restrict__ cst_g, const float* __restrict__ snt_g,
                         const float* __restrict__ a_r, const float* __restrict__ b_r,
                         float* __restrict__ ctx)
{
    extern __shared__ float sm[];
    int win = blockIdx.x >> 4;
    int h = blockIdx.x & 15;
    int tid = threadIdx.x;
    int warp = tid >> 5, lane = tid & 31;
    int base = win * 64;
    const float scale = 0.17677669529663687f;   // 1/sqrt(32)

    // ---- load Q,K,V (64x32 each), scale Q ----
    for (int idx = tid; idx < 512; idx += 128) {
        int row = idx >> 3, seg = idx & 7;
        const float* rp = qkv + (size_t)(base + row) * (3 * Cc) + h * HD + seg * 4;
        float4 q4 = *(const float4*)(rp);
        q4.x *= scale; q4.y *= scale; q4.z *= scale; q4.w *= scale;
        *(float4*)(sm + A_QS + row * 36 + seg * 4) = q4;
        *(float4*)(sm + A_KS + row * 36 + seg * 4) = *(const float4*)(rp + Cc);
        *(float4*)(sm + A_VS + row * 36 + seg * 4) = *(const float4*)(rp + 2 * Cc);
    }
    // aphi slice for this head (64x64)
    for (int idx = tid; idx < 1024; idx += 128)
        *(float4*)(sm + A_AP + idx * 4) = *(const float4*)(aphi + h * 4096 + idx * 4);
    // radial tables for this window
    for (int idx = tid; idx < 240; idx += 128) {
        *(float4*)(sm + A_CT + idx * 4) = *(const float4*)(cst_g + win * 960 + idx * 4);
        *(float4*)(sm + A_ST + idx * 4) = *(const float4*)(snt_g + win * 960 + idx * 4);
    }
    // a_r/b_r reindexed to rad+7 convention
    if (tid < 15) {
        int rad = tid - 7;
        int ira = rad < 0 ? rad + 15 : rad;
        sm[A_AR + tid] = a_r[ira * 16 + h];
        sm[A_BR + tid] = b_r[ira * 16 + h];
    }
    __syncthreads();

    const int qrow = lane >> 2, l3 = lane & 3;
    const int wrow = warp * 16;
    const int iL = wrow + qrow, iH = iL + 8;

    // ---- S = Q K^T via mma ----
    float acc[8][4];
    #pragma unroll
    for (int nt = 0; nt < 8; nt++)
        #pragma unroll
        for (int q = 0; q < 4; q++) acc[nt][q] = 0.0f;

    float afr[4][4];
    #pragma unroll
    for (int kk = 0; kk < 4; kk++) {
        int c = kk * 8 + l3;
        afr[kk][0] = sm[A_QS + iL * 36 + c];
        afr[kk][1] = sm[A_QS + iH * 36 + c];
        afr[kk][2] = sm[A_QS + iL * 36 + c + 4];
        afr[kk][3] = sm[A_QS + iH * 36 + c + 4];
    }
    #pragma unroll
    for (int nt = 0; nt < 8; nt++) {
        int nrow = nt * 8 + qrow;
        #pragma unroll
        for (int kk = 0; kk < 4; kk++) {
            float b0 = sm[A_KS + nrow * 36 + kk * 8 + l3];
            float b1 = sm[A_KS + nrow * 36 + kk * 8 + l3 + 4];
            mma_tf32_f(acc[nt], afr[kk], b0, b1);
        }
    }

    // ---- bias + softmax ----
    float mlo = -1e30f, mhi = -1e30f;
    #pragma unroll
    for (int nt = 0; nt < 8; nt++) {
        int irL = 2 * warp - nt + 7;   // rad+7 for low rows (i>>3 = 2w)
        int irH = irL + 1;
        int j0 = nt * 8 + 2 * l3;
        float aL = sm[A_AR + irL], bL = sm[A_BR + irL];
        float aH = sm[A_AR + irH], bH = sm[A_BR + irH];
        acc[nt][0] += sm[A_AP + iL * 64 + j0]     + aL * sm[A_CT + irL * 64 + j0]     + bL * sm[A_ST + irL * 64 + j0];
        acc[nt][1] += sm[A_AP + iL * 64 + j0 + 1] + aL * sm[A_CT + irL * 64 + j0 + 1] + bL * sm[A_ST + irL * 64 + j0 + 1];
        acc[nt][2] += sm[A_AP + iH * 64 + j0]     + aH * sm[A_CT + irH * 64 + j0]     + bH * sm[A_ST + irH * 64 + j0];
        acc[nt][3] += sm[A_AP + iH * 64 + j0 + 1] + aH * sm[A_CT + irH * 64 + j0 + 1] + bH * sm[A_ST + irH * 64 + j0 + 1];
        mlo = fmaxf(mlo, fmaxf(acc[nt][0], acc[nt][1]));
        mhi = fmaxf(mhi, fmaxf(acc[nt][2], acc[nt][3]));
    }
    mlo = fmaxf(mlo, __shfl_xor_sync(0xffffffffu, mlo, 1));
    mlo = fmaxf(mlo, __shfl_xor_sync(0xffffffffu, mlo, 2));
    mhi = fmaxf(mhi, __shfl_xor_sync(0xffffffffu, mhi, 1));
    mhi = fmaxf(mhi, __shfl_xor_sync(0xffffffffu, mhi, 2));

    float slo = 0.0f, shi = 0.0f;
    #pragma unroll
    for (int nt = 0; nt < 8; nt++) {
        acc[nt][0] = __expf(acc[nt][0] - mlo);
        acc[nt][1] = __expf(acc[nt][1] - mlo);
        acc[nt][2] = __expf(acc[nt][2] - mhi);
        acc[nt][3] = __expf(acc[nt][3] - mhi);
        slo += acc[nt][0] + acc[nt][1];
        shi += acc[nt][2] + acc[nt][3];
    }
    slo += __shfl_xor_sync(0xffffffffu, slo, 1);
    slo += __shfl_xor_sync(0xffffffffu, slo, 2);
    shi += __shfl_xor_sync(0xffffffffu, shi, 1);
    shi += __shfl_xor_sync(0xffffffffu, shi, 2);
    float invL = 1.0f / slo, invH = 1.0f / shi;

    // write P into S buffer (warp-private rows)
    #pragma unroll
    for (int nt = 0; nt < 8; nt++) {
        int j0 = nt * 8 + 2 * l3;
        float2 plo; plo.x = acc[nt][0]; plo.y = acc[nt][1];
        float2 phi; phi.x = acc[nt][2]; phi.y = acc[nt][3];
        *(float2*)(sm + A_SS + iL * 68 + j0) = plo;
        *(float2*)(sm + A_SS + iH * 68 + j0) = phi;
    }
    __syncwarp();

    // ---- O = P V via mma ----
    float oacc[4][4];
    #pragma unroll
    for (int nt = 0; nt < 4; nt++)
        #pragma unroll
        for (int q = 0; q < 4; q++) oacc[nt][q] = 0.0f;

    #pragma unroll
    for (int kk = 0; kk < 8; kk++) {
        float pa[4];
        int c = kk * 8 + l3;
        pa[0] = sm[A_SS + iL * 68 + c];
        pa[1] = sm[A_SS + iH * 68 + c];
        pa[2] = sm[A_SS + iL * 68 + c + 4];
        pa[3] = sm[A_SS + iH * 68 + c + 4];
        #pragma unroll
        for (int nt = 0; nt < 4; nt++) {
            float b0 = sm[A_VS + (kk * 8 + l3) * 36 + nt * 8 + qrow];
            float b1 = sm[A_VS + (kk * 8 + l3 + 4) * 36 + nt * 8 + qrow];
            mma_tf32_f(oacc[nt], pa, b0, b1);
        }
    }

    // ---- epilogue: scale by 1/sum, write ctx ----
    #pragma unroll
    for (int nt = 0; nt < 4; nt++) {
        int d0 = nt * 8 + 2 * l3;
        float2 lo; lo.x = oacc[nt][0] * invL; lo.y = oacc[nt][1] * invL;
        float2 hi; hi.x = oacc[nt][2] * invH; hi.y = oacc[nt][3] * invH;
        *(float2*)(ctx + (size_t)(base + iL) * Cc + h * HD + d0) = lo;
        *(float2*)(ctx + (size_t)(base + iH) * Cc + h * HD + d0) = hi;
    }
}

// ---------------- launch ----------------
#define GEMM_SMEM (3 * GSTAGE)

extern "C" void kernel_launch(void* const* d_in, const int* in_sizes, int n_in,
                              void* d_out, int out_size)
{
    const float* x       = (const float*)d_in[0];
    const float* D       = (const float*)d_in[1];
    const float* norm1_g = (const float*)d_in[2];
    const float* norm1_b = (const float*)d_in[3];
    const float* qkv_w   = (const float*)d_in[4];
    const float* qkv_b   = (const float*)d_in[5];
    const float* proj_w  = (const float*)d_in[6];
    const float* proj_b  = (const float*)d_in[7];
    const float* a_p     = (const float*)d_in[8];
    const float* b_p     = (const float*)d_in[9];
    const float* a_r     = (const float*)d_in[10];
    const float* b_r     = (const float*)d_in[11];
    const float* norm2_g = (const float*)d_in[12];
    const float* norm2_b = (const float*)d_in[13];
    const float* fc1_w   = (const float*)d_in[14];
    const float* fc1_b   = (const float*)d_in[15];
    const float* fc2_w   = (const float*)d_in[16];
    const float* fc2_b   = (const float*)d_in[17];
    float* out = (float*)d_out;

    float *p_xw, *p_dw, *p_qkv, *p_ctx, *p_x2, *p_xn2, *p_h, *p_aphi, *p_cst, *p_snt;
    cudaGetSymbolAddress((void**)&p_xw,   g_xw);
    cudaGetSymbolAddress((void**)&p_dw,   g_dw);
    cudaGetSymbolAddress((void**)&p_qkv,  g_qkv);
    cudaGetSymbolAddress((void**)&p_ctx,  g_ctx);
    cudaGetSymbolAddress((void**)&p_x2,   g_x2);
    cudaGetSymbolAddress((void**)&p_xn2,  g_xn2);
    cudaGetSymbolAddress((void**)&p_h,    g_h);
    cudaGetSymbolAddress((void**)&p_aphi, g_aphi);
    cudaGetSymbolAddress((void**)&p_cst,  g_cst);
    cudaGetSymbolAddress((void**)&p_snt,  g_snt);

    cudaFuncSetAttribute(gemm_mma<0>, cudaFuncAttributeMaxDynamicSharedMemorySize, GEMM_SMEM);
    cudaFuncSetAttribute(gemm_mma<1>, cudaFuncAttributeMaxDynamicSharedMemorySize, GEMM_SMEM);
    cudaFuncSetAttribute(gemm_mma<2>, cudaFuncAttributeMaxDynamicSharedMemorySize, GEMM_SMEM);
    cudaFuncSetAttribute(gemm_mma<3>, cudaFuncAttributeMaxDynamicSharedMemorySize, GEMM_SMEM);
    cudaFuncSetAttribute(attn_mma, cudaFuncAttributeMaxDynamicSharedMemorySize, ATTN_SMEM);

    // 1. azimuth bias table
    aphi_kernel<<<(NHh * Nn * Nn + 255) / 256, 256>>>(a_p, b_p);

    // 2. LN1 + window partition
    ln_kernel<true><<<MROWS, 128>>>(x, norm1_g, norm1_b, D, p_xw, p_dw);

    // 3. radial sincos tables (needs p_dw)
    rtab_kernel<<<(NWIN * 15 * 64 + 255) / 256, 256>>>(p_dw);

    // 4. QKV GEMM (65536 x 512) @ (512 x 1536)
    gemm_mma<0><<<dim3(3 * Cc / 256, MROWS / 128), 256, GEMM_SMEM>>>(
        p_xw, qkv_w, qkv_b, nullptr, p_qkv, MROWS, 3 * Cc, Cc);

    // 5. attention (tensor core)
    attn_mma<<<NWIN * NHh, 128, ATTN_SMEM>>>(p_qkv, p_aphi, p_cst, p_snt, a_r, b_r, p_ctx);

    // 6. proj GEMM + window reverse + residual
    gemm_mma<1><<<dim3(Cc / 256, MROWS / 128), 256, GEMM_SMEM>>>(
        p_ctx, proj_w, proj_b, x, p_x2, MROWS, Cc, Cc);

    // 7. LN2
    ln_kernel<false><<<MROWS, 128>>>(p_x2, norm2_g, norm2_b, nullptr, p_xn2, nullptr);

    // 8. fc1 + GELU
    gemm_mma<2><<<dim3(HID / 256, MROWS / 128), 256, GEMM_SMEM>>>(
        p_xn2, fc1_w, fc1_b, nullptr, p_h, MROWS, HID, Cc);

    // 9. fc2 + residual -> out
    gemm_mma<3><<<dim3(Cc / 256, MROWS / 128), 256, GEMM_SMEM>>>(
        p_h, fc2_w, fc2_b, p_x2, out, MROWS, Cc, HID);
}

// round 6
// speedup vs baseline: 4.2700x; 1.0110x over previous
#include <cuda_runtime.h>
#include <cuda_bf16.h>
#include <cstdint>

// ---------------- problem constants ----------------
#define B_    16
#define Hh    64
#define WRES  64
#define Cc    512
#define NHh   16
#define Nn    64
#define HD    32
#define HID   2048
#define NWIN  1024
#define MROWS 65536
#define PI_F  3.14159265358979323846f

// ---------------- scratch ----------------
__device__ float g_xw [MROWS * Cc];
__device__ float g_dw [MROWS];
__device__ float g_qkv[MROWS * 3 * Cc];
__device__ float g_ctx[MROWS * Cc];
__device__ float g_x2 [MROWS * Cc];
__device__ float g_xn2[MROWS * Cc];
__device__ float g_h  [MROWS * HID];
__device__ float g_aphi[NHh * Nn * Nn];
__device__ float g_cst[NWIN * 15 * 64];
__device__ float g_snt[NWIN * 15 * 64];

// ---------------- helpers ----------------
__device__ __forceinline__ uint32_t smem_u32(const void* p) {
    uint32_t a;
    asm("{ .reg .u64 t; cvta.to.shared.u64 t, %1; cvt.u32.u64 %0, t; }" : "=r"(a) : "l"(p));
    return a;
}
__device__ __forceinline__ void cp_async16(uint32_t saddr, const void* gaddr) {
    asm volatile("cp.async.cg.shared.global [%0], [%1], 16;" :: "r"(saddr), "l"(gaddr) : "memory");
}
__device__ __forceinline__ void cp_commit() {
    asm volatile("cp.async.commit_group;" ::: "memory");
}
template<int NN>
__device__ __forceinline__ void cp_wait() {
    asm volatile("cp.async.wait_group %0;" :: "n"(NN) : "memory");
}
__device__ __forceinline__ void ldmatrix4(uint32_t* r, uint32_t addr) {
    asm volatile("ldmatrix.sync.aligned.m8n8.x4.shared.b16 {%0,%1,%2,%3}, [%4];"
        : "=r"(r[0]), "=r"(r[1]), "=r"(r[2]), "=r"(r[3]) : "r"(addr));
}
__device__ __forceinline__ void mma_tf32(float* c, const uint32_t* a, const uint32_t* b) {
    asm volatile(
        "mma.sync.aligned.m16n8k8.row.col.f32.tf32.tf32.f32 "
        "{%0,%1,%2,%3}, {%4,%5,%6,%7}, {%8,%9}, {%0,%1,%2,%3};"
        : "+f"(c[0]), "+f"(c[1]), "+f"(c[2]), "+f"(c[3])
        : "r"(a[0]), "r"(a[1]), "r"(a[2]), "r"(a[3]), "r"(b[0]), "r"(b[1]));
}
__device__ __forceinline__ void mma_tf32_f(float* c, const float* a, float b0, float b1) {
    asm volatile(
        "mma.sync.aligned.m16n8k8.row.col.f32.tf32.tf32.f32 "
        "{%0,%1,%2,%3}, {%4,%5,%6,%7}, {%8,%9}, {%0,%1,%2,%3};"
        : "+f"(c[0]), "+f"(c[1]), "+f"(c[2]), "+f"(c[3])
        : "r"(__float_as_uint(a[0])), "r"(__float_as_uint(a[1])),
          "r"(__float_as_uint(a[2])), "r"(__float_as_uint(a[3])),
          "r"(__float_as_uint(b0)), "r"(__float_as_uint(b1)));
}

// ---------------- A_phi precompute ----------------
__global__ void aphi_kernel(const float* __restrict__ a_p, const float* __restrict__ b_p)
{
    int idx = blockIdx.x * blockDim.x + threadIdx.x;
    if (idx >= NHh * Nn * Nn) return;
    int h = idx >> 12;
    int rem = idx & 4095;
    int i = rem >> 6, j = rem & 63;
    int az = (i & 7) - (j & 7);
    int ip = az < 0 ? az + 15 : az;
    float azf = (float)az * (2.0f * PI_F / (float)WRES);
    g_aphi[idx] = a_p[ip * NHh + h] * cosf(azf) + b_p[ip * NHh + h] * sinf(azf);
}

// ---------------- radial sincos tables: [win][rad+7][j] ----------------
__global__ void rtab_kernel(const float* __restrict__ dw)
{
    int idx = blockIdx.x * blockDim.x + threadIdx.x;
    if (idx >= NWIN * 15 * 64) return;
    int win = idx / 960;
    int rem = idx - win * 960;
    int ir = rem >> 6;
    int j = rem & 63;
    float ang = (float)(ir - 7) * dw[win * 64 + j] * (2.0f * PI_F / 256.0f);
    float sn, cs;
    sincosf(ang, &sn, &cs);
    g_cst[idx] = cs;
    g_snt[idx] = sn;
}

// ---------------- LayerNorm (+ optional window partition) ----------------
template<bool PERM>
__launch_bounds__(128)
__global__ void ln_kernel(const float* __restrict__ x, const float* __restrict__ g,
                          const float* __restrict__ b, const float* __restrict__ D,
                          float* __restrict__ out, float* __restrict__ dwout)
{
    int r = blockIdx.x;
    int tid = threadIdx.x;
    float4 v = ((const float4*)(x + (size_t)r * Cc))[tid];
    float s = v.x + v.y + v.z + v.w;
    float sq = v.x * v.x + v.y * v.y + v.z * v.z + v.w * v.w;
    #pragma unroll
    for (int o = 16; o; o >>= 1) {
        s += __shfl_xor_sync(0xffffffffu, s, o);
        sq += __shfl_xor_sync(0xffffffffu, sq, o);
    }
    __shared__ float ss[4], sqs[4];
    int w = tid >> 5;
    if ((tid & 31) == 0) { ss[w] = s; sqs[w] = sq; }
    __syncthreads();
    s = ss[0] + ss[1] + ss[2] + ss[3];
    sq = sqs[0] + sqs[1] + sqs[2] + sqs[3];
    float mean = s * (1.0f / Cc);
    float var = sq * (1.0f / Cc) - mean * mean;
    float rstd = rsqrtf(var + 1e-5f);
    float4 gg = ((const float4*)g)[tid];
    float4 bb = ((const float4*)b)[tid];
    float4 o;
    o.x = (v.x - mean) * rstd * gg.x + bb.x;
    o.y = (v.y - mean) * rstd * gg.y + bb.y;
    o.z = (v.z - mean) * rstd * gg.z + bb.z;
    o.w = (v.w - mean) * rstd * gg.w + bb.w;
    int dst = r;
    if (PERM) {
        int bI = r >> 12;
        int hh = (r >> 6) & 63;
        int wc = r & 63;
        int win = bI * 64 + (hh >> 3) * 8 + (wc >> 3);
        int rin = (hh & 7) * 8 + (wc & 7);
        dst = win * 64 + rin;
        if (tid == 0) dwout[dst] = D[r];
    }
    ((float4*)(out + (size_t)dst * Cc))[tid] = o;
}

// ============ tf32 mma.sync GEMM: Y = A(MxK) @ W^T (W NoutxK) + bias ============
// Tile BM=128, BN=128, BK=32. 3-stage cp.async pipeline, one barrier/iter.
// 8 warps, warp tile 64x32. 2 CTAs/SM.
// MODE 0: plain   MODE 1: window-reverse + residual   MODE 2: GELU   MODE 3: residual
#define GSTAGE 32768
template<int MODE>
__launch_bounds__(256, 2)
__global__ void gemm_mma(const float* __restrict__ A, const float* __restrict__ W,
                         const float* __restrict__ bias, const float* __restrict__ res,
                         float* __restrict__ out, int M, int N, int K)
{
    extern __shared__ char smem[];
    const uint32_t sbase = smem_u32(smem);   // stage s: A (16KB) then B (16KB)
    const int tid = threadIdx.x;
    const int bm = blockIdx.y * 128;
    const int bn = blockIdx.x * 128;
    const int warp = tid >> 5, lane = tid & 31;
    const int wm = warp & 1;      // 2 warps over M (64 rows each)
    const int wn = warp >> 1;     // 4 warps over N (32 cols each)

    float acc[4][4][4];
    #pragma unroll
    for (int i = 0; i < 4; i++)
        #pragma unroll
        for (int j = 0; j < 4; j++)
            #pragma unroll
            for (int q = 0; q < 4; q++) acc[i][j][q] = 0.0f;

    const int nk = K >> 5;

    auto prefetch = [&](int kt, int stage) {
        uint32_t ab = sbase + (uint32_t)stage * GSTAGE;
        uint32_t bb = ab + 16384u;
        const float* Ap = A + (size_t)bm * K + (size_t)kt * 32;
        const float* Wp = W + (size_t)bn * K + (size_t)kt * 32;
        #pragma unroll
        for (int t = 0; t < 4; t++) {
            int idx = tid + t * 256;
            int row = idx >> 3, seg = idx & 7;
            uint32_t so = (uint32_t)(row * 128 + ((seg ^ (row & 7)) << 4));
            cp_async16(ab + so, Ap + (size_t)row * K + seg * 4);
            cp_async16(bb + so, Wp + (size_t)row * K + seg * 4);
        }
    };

    prefetch(0, 0); cp_commit();
    prefetch(1, 1); cp_commit();

    for (int kt = 0; kt < nk; kt++) {
        cp_wait<1>();
        __syncthreads();
        if (kt + 2 < nk) {
            int st = (kt + 2) % 3;
            prefetch(kt + 2, st);
        }
        cp_commit();

        uint32_t ab = sbase + (uint32_t)(kt % 3) * GSTAGE;
        uint32_t bb = ab + 16384u;

        #pragma unroll
        for (int ks = 0; ks < 4; ks++) {
            uint32_t af[4][4];
            uint32_t bf[4][2];
            #pragma unroll
            for (int am = 0; am < 4; am++) {
                int row = wm * 64 + am * 16 + ((lane >> 3) & 1) * 8 + (lane & 7);
                int koff = ks * 32 + (lane >> 4) * 16;
                uint32_t addr = ab + (uint32_t)(row * 128 + (koff ^ ((row & 7) << 4)));
                ldmatrix4(af[am], addr);
            }
            #pragma unroll
            for (int bp = 0; bp < 2; bp++) {
                int nrow = wn * 32 + bp * 16 + ((lane >> 4) & 1) * 8 + (lane & 7);
                int koff = ks * 32 + ((lane >> 3) & 1) * 16;
                uint32_t addr = bb + (uint32_t)(nrow * 128 + (koff ^ ((nrow & 7) << 4)));
                uint32_t r[4];
                ldmatrix4(r, addr);
                bf[bp * 2 + 0][0] = r[0]; bf[bp * 2 + 0][1] = r[1];
                bf[bp * 2 + 1][0] = r[2]; bf[bp * 2 + 1][1] = r[3];
            }
            #pragma unroll
            for (int am = 0; am < 4; am++)
                #pragma unroll
                for (int an = 0; an < 4; an++)
                    mma_tf32(acc[am][an], af[am], bf[an]);
        }
    }

    // ---------------- epilogue ----------------
    #pragma unroll
    for (int am = 0; am < 4; am++) {
        #pragma unroll
        for (int half = 0; half < 2; half++) {
            int m = bm + wm * 64 + am * 16 + half * 8 + (lane >> 2);
            size_t obase;
            if (MODE == 1) {
                int win = m >> 6, rin = m & 63;
                int bI = win >> 6, wb = (win >> 3) & 7, wwi = win & 7;
                int hh = wb * 8 + (rin >> 3);
                int wc = wwi * 8 + (rin & 7);
                obase = (size_t)(bI * (Hh * WRES) + hh * 64 + wc) * N;
            } else {
                obase = (size_t)m * N;
            }
            #pragma unroll
            for (int an = 0; an < 4; an++) {
                int n = bn + wn * 32 + an * 8 + (lane & 3) * 2;
                float2 bv = *(const float2*)(bias + n);
                float x0 = acc[am][an][half * 2 + 0] + bv.x;
                float x1 = acc[am][an][half * 2 + 1] + bv.y;
                if (MODE == 2) {
                    x0 = 0.5f * x0 * (1.0f + erff(x0 * 0.70710678118654752f));
                    x1 = 0.5f * x1 * (1.0f + erff(x1 * 0.70710678118654752f));
                }
                if (MODE == 1 || MODE == 3) {
                    float2 rv = *(const float2*)(res + obase + n);
                    x0 += rv.x; x1 += rv.y;
                }
                float2 o; o.x = x0; o.y = x1;
                *(float2*)(out + obase + n) = o;
            }
        }
    }
}

// ============ tensor-core attention per (window, head) ============
#define A_QS 0
#define A_KS 2304
#define A_VS 4608
#define A_SS 6912      /* 64 x 68 */
#define A_AP 11264     /* 4096 */
#define A_CT 15360     /* 960 */
#define A_ST 16320     /* 960 */
#define A_AR 17280     /* 16 */
#define A_BR 17296     /* 16 */
#define ATTN_SMEM (17312 * 4)

__launch_bounds__(128)
__global__ void attn_mma(const float* __restrict__ qkv,
                         const float* __restrict__ aphi,
                         const float* __restrict__ cst_g, const float* __restrict__ snt_g,
                         const float* __restrict__ a_r, const float* __restrict__ b_r,
                         float* __restrict__ ctx)
{
    extern __shared__ float sm[];
    int win = blockIdx.x >> 4;
    int h = blockIdx.x & 15;
    int tid = threadIdx.x;
    int warp = tid >> 5, lane = tid & 31;
    int base = win * 64;
    const float scale = 0.17677669529663687f;

    for (int idx = tid; idx < 512; idx += 128) {
        int row = idx >> 3, seg = idx & 7;
        const float* rp = qkv + (size_t)(base + row) * (3 * Cc) + h * HD + seg * 4;
        float4 q4 = *(const float4*)(rp);
        q4.x *= scale; q4.y *= scale; q4.z *= scale; q4.w *= scale;
        *(float4*)(sm + A_QS + row * 36 + seg * 4) = q4;
        *(float4*)(sm + A_KS + row * 36 + seg * 4) = *(const float4*)(rp + Cc);
        *(float4*)(sm + A_VS + row * 36 + seg * 4) = *(const float4*)(rp + 2 * Cc);
    }
    for (int idx = tid; idx < 1024; idx += 128)
        *(float4*)(sm + A_AP + idx * 4) = *(const float4*)(aphi + h * 4096 + idx * 4);
    for (int idx = tid; idx < 240; idx += 128) {
        *(float4*)(sm + A_CT + idx * 4) = *(const float4*)(cst_g + win * 960 + idx * 4);
        *(float4*)(sm + A_ST + idx * 4) = *(const float4*)(snt_g + win * 960 + idx * 4);
    }
    if (tid < 15) {
        int rad = tid - 7;
        int ira = rad < 0 ? rad + 15 : rad;
        sm[A_AR + tid] = a_r[ira * 16 + h];
        sm[A_BR + tid] = b_r[ira * 16 + h];
    }
    __syncthreads();

    const int qrow = lane >> 2, l3 = lane & 3;
    const int wrow = warp * 16;
    const int iL = wrow + qrow, iH = iL + 8;

    float acc[8][4];
    #pragma unroll
    for (int nt = 0; nt < 8; nt++)
        #pragma unroll
        for (int q = 0; q < 4; q++) acc[nt][q] = 0.0f;

    float afr[4][4];
    #pragma unroll
    for (int kk = 0; kk < 4; kk++) {
        int c = kk * 8 + l3;
        afr[kk][0] = sm[A_QS + iL * 36 + c];
        afr[kk][1] = sm[A_QS + iH * 36 + c];
        afr[kk][2] = sm[A_QS + iL * 36 + c + 4];
        afr[kk][3] = sm[A_QS + iH * 36 + c + 4];
    }
    #pragma unroll
    for (int nt = 0; nt < 8; nt++) {
        int nrow = nt * 8 + qrow;
        #pragma unroll
        for (int kk = 0; kk < 4; kk++) {
            float b0 = sm[A_KS + nrow * 36 + kk * 8 + l3];
            float b1 = sm[A_KS + nrow * 36 + kk * 8 + l3 + 4];
            mma_tf32_f(acc[nt], afr[kk], b0, b1);
        }
    }

    float mlo = -1e30f, mhi = -1e30f;
    #pragma unroll
    for (int nt = 0; nt < 8; nt++) {
        int irL = 2 * warp - nt + 7;
        int irH = irL + 1;
        int j0 = nt * 8 + 2 * l3;
        float aL = sm[A_AR + irL], bL = sm[A_BR + irL];
        float aH = sm[A_AR + irH], bH = sm[A_BR + irH];
        acc[nt][0] += sm[A_AP + iL * 64 + j0]     + aL * sm[A_CT + irL * 64 + j0]     + bL * sm[A_ST + irL * 64 + j0];
        acc[nt][1] += sm[A_AP + iL * 64 + j0 + 1] + aL * sm[A_CT + irL * 64 + j0 + 1] + bL * sm[A_ST + irL * 64 + j0 + 1];
        acc[nt][2] += sm[A_AP + iH * 64 + j0]     + aH * sm[A_CT + irH * 64 + j0]     + bH * sm[A_ST + irH * 64 + j0];
        acc[nt][3] += sm[A_AP + iH * 64 + j0 + 1] + aH * sm[A_CT + irH * 64 + j0 + 1] + bH * sm[A_ST + irH * 64 + j0 + 1];
        mlo = fmaxf(mlo, fmaxf(acc[nt][0], acc[nt][1]));
        mhi = fmaxf(mhi, fmaxf(acc[nt][2], acc[nt][3]));
    }
    mlo = fmaxf(mlo, __shfl_xor_sync(0xffffffffu, mlo, 1));
    mlo = fmaxf(mlo, __shfl_xor_sync(0xffffffffu, mlo, 2));
    mhi = fmaxf(mhi, __shfl_xor_sync(0xffffffffu, mhi, 1));
    mhi = fmaxf(mhi, __shfl_xor_sync(0xffffffffu, mhi, 2));

    float slo = 0.0f, shi = 0.0f;
    #pragma unroll
    for (int nt = 0; nt < 8; nt++) {
        acc[nt][0] = __expf(acc[nt][0] - mlo);
        acc[nt][1] = __expf(acc[nt][1] - mlo);
        acc[nt][2] = __expf(acc[nt][2] - mhi);
        acc[nt][3] = __expf(acc[nt][3] - mhi);
        slo += acc[nt][0] + acc[nt][1];
        shi += acc[nt][2] + acc[nt][3];
    }
    slo += __shfl_xor_sync(0xffffffffu, slo, 1);
    slo += __shfl_xor_sync(0xffffffffu, slo, 2);
    shi += __shfl_xor_sync(0xffffffffu, shi, 1);
    shi += __shfl_xor_sync(0xffffffffu, shi, 2);
    float invL = 1.0f / slo, invH = 1.0f / shi;

    #pragma unroll
    for (int nt = 0; nt < 8; nt++) {
        int j0 = nt * 8 + 2 * l3;
        float2 plo; plo.x = acc[nt][0]; plo.y = acc[nt][1];
        float2 phi; phi.x = acc[nt][2]; phi.y = acc[nt][3];
        *(float2*)(sm + A_SS + iL * 68 + j0) = plo;
        *(float2*)(sm + A_SS + iH * 68 + j0) = phi;
    }
    __syncwarp();

    float oacc[4][4];
    #pragma unroll
    for (int nt = 0; nt < 4; nt++)
        #pragma unroll
        for (int q = 0; q < 4; q++) oacc[nt][q] = 0.0f;

    #pragma unroll
    for (int kk = 0; kk < 8; kk++) {
        float pa[4];
        int c = kk * 8 + l3;
        pa[0] = sm[A_SS + iL * 68 + c];
        pa[1] = sm[A_SS + iH * 68 + c];
        pa[2] = sm[A_SS + iL * 68 + c + 4];
        pa[3] = sm[A_SS + iH * 68 + c + 4];
        #pragma unroll
        for (int nt = 0; nt < 4; nt++) {
            float b0 = sm[A_VS + (kk * 8 + l3) * 36 + nt * 8 + qrow];
            float b1 = sm[A_VS + (kk * 8 + l3 + 4) * 36 + nt * 8 + qrow];
            mma_tf32_f(oacc[nt], pa, b0, b1);
        }
    }

    #pragma unroll
    for (int nt = 0; nt < 4; nt++) {
        int d0 = nt * 8 + 2 * l3;
        float2 lo; lo.x = oacc[nt][0] * invL; lo.y = oacc[nt][1] * invL;
        float2 hi; hi.x = oacc[nt][2] * invH; hi.y = oacc[nt][3] * invH;
        *(float2*)(ctx + (size_t)(base + iL) * Cc + h * HD + d0) = lo;
        *(float2*)(ctx + (size_t)(base + iH) * Cc + h * HD + d0) = hi;
    }
}

// ---------------- launch ----------------
#define GEMM_SMEM (3 * GSTAGE)

extern "C" void kernel_launch(void* const* d_in, const int* in_sizes, int n_in,
                              void* d_out, int out_size)
{
    const float* x       = (const float*)d_in[0];
    const float* D       = (const float*)d_in[1];
    const float* norm1_g = (const float*)d_in[2];
    const float* norm1_b = (const float*)d_in[3];
    const float* qkv_w   = (const float*)d_in[4];
    const float* qkv_b   = (const float*)d_in[5];
    const float* proj_w  = (const float*)d_in[6];
    const float* proj_b  = (const float*)d_in[7];
    const float* a_p     = (const float*)d_in[8];
    const float* b_p     = (const float*)d_in[9];
    const float* a_r     = (const float*)d_in[10];
    const float* b_r     = (const float*)d_in[11];
    const float* norm2_g = (const float*)d_in[12];
    const float* norm2_b = (const float*)d_in[13];
    const float* fc1_w   = (const float*)d_in[14];
    const float* fc1_b   = (const float*)d_in[15];
    const float* fc2_w   = (const float*)d_in[16];
    const float* fc2_b   = (const float*)d_in[17];
    float* out = (float*)d_out;

    float *p_xw, *p_dw, *p_qkv, *p_ctx, *p_x2, *p_xn2, *p_h, *p_aphi, *p_cst, *p_snt;
    cudaGetSymbolAddress((void**)&p_xw,   g_xw);
    cudaGetSymbolAddress((void**)&p_dw,   g_dw);
    cudaGetSymbolAddress((void**)&p_qkv,  g_qkv);
    cudaGetSymbolAddress((void**)&p_ctx,  g_ctx);
    cudaGetSymbolAddress((void**)&p_x2,   g_x2);
    cudaGetSymbolAddress((void**)&p_xn2,  g_xn2);
    cudaGetSymbolAddress((void**)&p_h,    g_h);
    cudaGetSymbolAddress((void**)&p_aphi, g_aphi);
    cudaGetSymbolAddress((void**)&p_cst,  g_cst);
    cudaGetSymbolAddress((void**)&p_snt,  g_snt);

    cudaFuncSetAttribute(gemm_mma<0>, cudaFuncAttributeMaxDynamicSharedMemorySize, GEMM_SMEM);
    cudaFuncSetAttribute(gemm_mma<1>, cudaFuncAttributeMaxDynamicSharedMemorySize, GEMM_SMEM);
    cudaFuncSetAttribute(gemm_mma<2>, cudaFuncAttributeMaxDynamicSharedMemorySize, GEMM_SMEM);
    cudaFuncSetAttribute(gemm_mma<3>, cudaFuncAttributeMaxDynamicSharedMemorySize, GEMM_SMEM);
    cudaFuncSetAttribute(attn_mma, cudaFuncAttributeMaxDynamicSharedMemorySize, ATTN_SMEM);

    // 1. azimuth bias table
    aphi_kernel<<<(NHh * Nn * Nn + 255) / 256, 256>>>(a_p, b_p);

    // 2. LN1 + window partition
    ln_kernel<true><<<MROWS, 128>>>(x, norm1_g, norm1_b, D, p_xw, p_dw);

    // 3. radial sincos tables
    rtab_kernel<<<(NWIN * 15 * 64 + 255) / 256, 256>>>(p_dw);

    // 4. QKV GEMM
    gemm_mma<0><<<dim3(3 * Cc / 128, MROWS / 128), 256, GEMM_SMEM>>>(
        p_xw, qkv_w, qkv_b, nullptr, p_qkv, MROWS, 3 * Cc, Cc);

    // 5. attention (tensor core)
    attn_mma<<<NWIN * NHh, 128, ATTN_SMEM>>>(p_qkv, p_aphi, p_cst, p_snt, a_r, b_r, p_ctx);

    // 6. proj GEMM + window reverse + residual
    gemm_mma<1><<<dim3(Cc / 128, MROWS / 128), 256, GEMM_SMEM>>>(
        p_ctx, proj_w, proj_b, x, p_x2, MROWS, Cc, Cc);

    // 7. LN2
    ln_kernel<false><<<MROWS, 128>>>(p_x2, norm2_g, norm2_b, nullptr, p_xn2, nullptr);

    // 8. fc1 + GELU
    gemm_mma<2><<<dim3(HID / 128, MROWS / 128), 256, GEMM_SMEM>>>(
        p_xn2, fc1_w, fc1_b, nullptr, p_h, MROWS, HID, Cc);

    // 9. fc2 + residual -> out
    gemm_mma<3><<<dim3(Cc / 128, MROWS / 128), 256, GEMM_SMEM>>>(
        p_h, fc2_w, fc2_b, p_x2, out, MROWS, Cc, HID);
}

// round 7
// speedup vs baseline: 4.3118x; 1.0098x over previous
#include <cuda_runtime.h>
#include <cuda_bf16.h>
#include <cstdint>

// ---------------- problem constants ----------------
#define B_    16
#define Hh    64
#define WRES  64
#define Cc    512
#define NHh   16
#define Nn    64
#define HD    32
#define HID   2048
#define NWIN  1024
#define MROWS 65536
#define PI_F  3.14159265358979323846f

// ---------------- scratch ----------------
__device__ float g_xw [MROWS * Cc];
__device__ float g_dw [MROWS];
__device__ float g_qkv[MROWS * 3 * Cc];
__device__ float g_ctx[MROWS * Cc];
__device__ float g_x2 [MROWS * Cc];
__device__ float g_xn2[MROWS * Cc];
__device__ float g_h  [MROWS * HID];
__device__ float g_aphi[NHh * Nn * Nn];
__device__ float g_cst[NWIN * 15 * 64];
__device__ float g_snt[NWIN * 15 * 64];

// ---------------- helpers ----------------
__device__ __forceinline__ uint32_t smem_u32(const void* p) {
    uint32_t a;
    asm("{ .reg .u64 t; cvta.to.shared.u64 t, %1; cvt.u32.u64 %0, t; }" : "=r"(a) : "l"(p));
    return a;
}
__device__ __forceinline__ void cp_async16(uint32_t saddr, const void* gaddr) {
    asm volatile("cp.async.cg.shared.global [%0], [%1], 16;" :: "r"(saddr), "l"(gaddr) : "memory");
}
__device__ __forceinline__ void cp_commit() {
    asm volatile("cp.async.commit_group;" ::: "memory");
}
template<int NN>
__device__ __forceinline__ void cp_wait() {
    asm volatile("cp.async.wait_group %0;" :: "n"(NN) : "memory");
}
__device__ __forceinline__ void ldmatrix4(uint32_t* r, uint32_t addr) {
    asm volatile("ldmatrix.sync.aligned.m8n8.x4.shared.b16 {%0,%1,%2,%3}, [%4];"
        : "=r"(r[0]), "=r"(r[1]), "=r"(r[2]), "=r"(r[3]) : "r"(addr));
}
__device__ __forceinline__ void mma_tf32(float* c, const uint32_t* a, const uint32_t* b) {
    asm volatile(
        "mma.sync.aligned.m16n8k8.row.col.f32.tf32.tf32.f32 "
        "{%0,%1,%2,%3}, {%4,%5,%6,%7}, {%8,%9}, {%0,%1,%2,%3};"
        : "+f"(c[0]), "+f"(c[1]), "+f"(c[2]), "+f"(c[3])
        : "r"(a[0]), "r"(a[1]), "r"(a[2]), "r"(a[3]), "r"(b[0]), "r"(b[1]));
}
__device__ __forceinline__ void mma_tf32_f(float* c, const float* a, float b0, float b1) {
    asm volatile(
        "mma.sync.aligned.m16n8k8.row.col.f32.tf32.tf32.f32 "
        "{%0,%1,%2,%3}, {%4,%5,%6,%7}, {%8,%9}, {%0,%1,%2,%3};"
        : "+f"(c[0]), "+f"(c[1]), "+f"(c[2]), "+f"(c[3])
        : "r"(__float_as_uint(a[0])), "r"(__float_as_uint(a[1])),
          "r"(__float_as_uint(a[2])), "r"(__float_as_uint(a[3])),
          "r"(__float_as_uint(b0)), "r"(__float_as_uint(b1)));
}

// ---------------- A_phi precompute ----------------
__global__ void aphi_kernel(const float* __restrict__ a_p, const float* __restrict__ b_p)
{
    int idx = blockIdx.x * blockDim.x + threadIdx.x;
    if (idx >= NHh * Nn * Nn) return;
    int h = idx >> 12;
    int rem = idx & 4095;
    int i = rem >> 6, j = rem & 63;
    int az = (i & 7) - (j & 7);
    int ip = az < 0 ? az + 15 : az;
    float azf = (float)az * (2.0f * PI_F / (float)WRES);
    g_aphi[idx] = a_p[ip * NHh + h] * cosf(azf) + b_p[ip * NHh + h] * sinf(azf);
}

// ---------------- radial sincos tables: [win][rad+7][j] ----------------
__global__ void rtab_kernel(const float* __restrict__ dw)
{
    int idx = blockIdx.x * blockDim.x + threadIdx.x;
    if (idx >= NWIN * 15 * 64) return;
    int win = idx / 960;
    int rem = idx - win * 960;
    int ir = rem >> 6;
    int j = rem & 63;
    float ang = (float)(ir - 7) * dw[win * 64 + j] * (2.0f * PI_F / 256.0f);
    float sn, cs;
    sincosf(ang, &sn, &cs);
    g_cst[idx] = cs;
    g_snt[idx] = sn;
}

// ---------------- LayerNorm (+ optional window partition) ----------------
template<bool PERM>
__launch_bounds__(128)
__global__ void ln_kernel(const float* __restrict__ x, const float* __restrict__ g,
                          const float* __restrict__ b, const float* __restrict__ D,
                          float* __restrict__ out, float* __restrict__ dwout)
{
    int r = blockIdx.x;
    int tid = threadIdx.x;
    float4 v = ((const float4*)(x + (size_t)r * Cc))[tid];
    float s = v.x + v.y + v.z + v.w;
    float sq = v.x * v.x + v.y * v.y + v.z * v.z + v.w * v.w;
    #pragma unroll
    for (int o = 16; o; o >>= 1) {
        s += __shfl_xor_sync(0xffffffffu, s, o);
        sq += __shfl_xor_sync(0xffffffffu, sq, o);
    }
    __shared__ float ss[4], sqs[4];
    int w = tid >> 5;
    if ((tid & 31) == 0) { ss[w] = s; sqs[w] = sq; }
    __syncthreads();
    s = ss[0] + ss[1] + ss[2] + ss[3];
    sq = sqs[0] + sqs[1] + sqs[2] + sqs[3];
    float mean = s * (1.0f / Cc);
    float var = sq * (1.0f / Cc) - mean * mean;
    float rstd = rsqrtf(var + 1e-5f);
    float4 gg = ((const float4*)g)[tid];
    float4 bb = ((const float4*)b)[tid];
    float4 o;
    o.x = (v.x - mean) * rstd * gg.x + bb.x;
    o.y = (v.y - mean) * rstd * gg.y + bb.y;
    o.z = (v.z - mean) * rstd * gg.z + bb.z;
    o.w = (v.w - mean) * rstd * gg.w + bb.w;
    int dst = r;
    if (PERM) {
        int bI = r >> 12;
        int hh = (r >> 6) & 63;
        int wc = r & 63;
        int win = bI * 64 + (hh >> 3) * 8 + (wc >> 3);
        int rin = (hh & 7) * 8 + (wc & 7);
        dst = win * 64 + rin;
        if (tid == 0) dwout[dst] = D[r];
    }
    ((float4*)(out + (size_t)dst * Cc))[tid] = o;
}

// ============ tf32 mma.sync GEMM: Y = A(MxK) @ W^T (W NoutxK) + bias ============
// Tile BM=128, BN=128, BK=32. 3-stage cp.async pipeline, one barrier/iter.
// 4 warps (128 threads), warp tile 64x64 -> A and B each read only 2x from SMEM.
// 2 CTAs/SM. MODE 0: plain  1: window-reverse+residual  2: GELU  3: residual
#define GSTAGE 32768
template<int MODE>
__launch_bounds__(128, 2)
__global__ void gemm_mma(const float* __restrict__ A, const float* __restrict__ W,
                         const float* __restrict__ bias, const float* __restrict__ res,
                         float* __restrict__ out, int M, int N, int K)
{
    extern __shared__ char smem[];
    const uint32_t sbase = smem_u32(smem);   // stage s: A (16KB) then B (16KB)
    const int tid = threadIdx.x;
    const int bm = blockIdx.y * 128;
    const int bn = blockIdx.x * 128;
    const int warp = tid >> 5, lane = tid & 31;
    const int wm = warp & 1;      // 2 warps over M (64 rows each)
    const int wn = warp >> 1;     // 2 warps over N (64 cols each)

    float acc[4][8][4];
    #pragma unroll
    for (int i = 0; i < 4; i++)
        #pragma unroll
        for (int j = 0; j < 8; j++)
            #pragma unroll
            for (int q = 0; q < 4; q++) acc[i][j][q] = 0.0f;

    const int nk = K >> 5;

    auto prefetch = [&](int kt, int stage) {
        uint32_t ab = sbase + (uint32_t)stage * GSTAGE;
        uint32_t bb = ab + 16384u;
        const float* Ap = A + (size_t)bm * K + (size_t)kt * 32;
        const float* Wp = W + (size_t)bn * K + (size_t)kt * 32;
        #pragma unroll
        for (int t = 0; t < 8; t++) {
            int idx = tid + t * 128;
            int row = idx >> 3, seg = idx & 7;
            uint32_t so = (uint32_t)(row * 128 + ((seg ^ (row & 7)) << 4));
            cp_async16(ab + so, Ap + (size_t)row * K + seg * 4);
            cp_async16(bb + so, Wp + (size_t)row * K + seg * 4);
        }
    };

    prefetch(0, 0); cp_commit();
    prefetch(1, 1); cp_commit();

    for (int kt = 0; kt < nk; kt++) {
        cp_wait<1>();
        __syncthreads();
        if (kt + 2 < nk) {
            int st = (kt + 2) % 3;
            prefetch(kt + 2, st);
        }
        cp_commit();

        uint32_t ab = sbase + (uint32_t)(kt % 3) * GSTAGE;
        uint32_t bb = ab + 16384u;

        #pragma unroll
        for (int ks = 0; ks < 4; ks++) {
            uint32_t af[4][4];
            uint32_t bf[8][2];
            #pragma unroll
            for (int am = 0; am < 4; am++) {
                int row = wm * 64 + am * 16 + ((lane >> 3) & 1) * 8 + (lane & 7);
                int koff = ks * 32 + (lane >> 4) * 16;
                uint32_t addr = ab + (uint32_t)(row * 128 + (koff ^ ((row & 7) << 4)));
                ldmatrix4(af[am], addr);
            }
            #pragma unroll
            for (int bp = 0; bp < 4; bp++) {
                int nrow = wn * 64 + bp * 16 + ((lane >> 4) & 1) * 8 + (lane & 7);
                int koff = ks * 32 + ((lane >> 3) & 1) * 16;
                uint32_t addr = bb + (uint32_t)(nrow * 128 + (koff ^ ((nrow & 7) << 4)));
                uint32_t r[4];
                ldmatrix4(r, addr);
                bf[bp * 2 + 0][0] = r[0]; bf[bp * 2 + 0][1] = r[1];
                bf[bp * 2 + 1][0] = r[2]; bf[bp * 2 + 1][1] = r[3];
            }
            #pragma unroll
            for (int am = 0; am < 4; am++)
                #pragma unroll
                for (int an = 0; an < 8; an++)
                    mma_tf32(acc[am][an], af[am], bf[an]);
        }
    }

    // ---------------- epilogue ----------------
    #pragma unroll
    for (int am = 0; am < 4; am++) {
        #pragma unroll
        for (int half = 0; half < 2; half++) {
            int m = bm + wm * 64 + am * 16 + half * 8 + (lane >> 2);
            size_t obase;
            if (MODE == 1) {
                int win = m >> 6, rin = m & 63;
                int bI = win >> 6, wb = (win >> 3) & 7, wwi = win & 7;
                int hh = wb * 8 + (rin >> 3);
                int wc = wwi * 8 + (rin & 7);
                obase = (size_t)(bI * (Hh * WRES) + hh * 64 + wc) * N;
            } else {
                obase = (size_t)m * N;
            }
            #pragma unroll
            for (int an = 0; an < 8; an++) {
                int n = bn + wn * 64 + an * 8 + (lane & 3) * 2;
                float2 bv = *(const float2*)(bias + n);
                float x0 = acc[am][an][half * 2 + 0] + bv.x;
                float x1 = acc[am][an][half * 2 + 1] + bv.y;
                if (MODE == 2) {
                    x0 = 0.5f * x0 * (1.0f + erff(x0 * 0.70710678118654752f));
                    x1 = 0.5f * x1 * (1.0f + erff(x1 * 0.70710678118654752f));
                }
                if (MODE == 1 || MODE == 3) {
                    float2 rv = *(const float2*)(res + obase + n);
                    x0 += rv.x; x1 += rv.y;
                }
                float2 o; o.x = x0; o.y = x1;
                *(float2*)(out + obase + n) = o;
            }
        }
    }
}

// ============ tensor-core attention per (window, head) ============
#define A_QS 0
#define A_KS 2304
#define A_VS 4608
#define A_SS 6912      /* 64 x 68 */
#define A_AP 11264     /* 4096 */
#define A_CT 15360     /* 960 */
#define A_ST 16320     /* 960 */
#define A_AR 17280     /* 16 */
#define A_BR 17296     /* 16 */
#define ATTN_SMEM (17312 * 4)

__launch_bounds__(128)
__global__ void attn_mma(const float* __restrict__ qkv,
                         const float* __restrict__ aphi,
                         const float* __restrict__ cst_g, const float* __restrict__ snt_g,
                         const float* __restrict__ a_r, const float* __restrict__ b_r,
                         float* __restrict__ ctx)
{
    extern __shared__ float sm[];
    int win = blockIdx.x >> 4;
    int h = blockIdx.x & 15;
    int tid = threadIdx.x;
    int warp = tid >> 5, lane = tid & 31;
    int base = win * 64;
    const float scale = 0.17677669529663687f;

    for (int idx = tid; idx < 512; idx += 128) {
        int row = idx >> 3, seg = idx & 7;
        const float* rp = qkv + (size_t)(base + row) * (3 * Cc) + h * HD + seg * 4;
        float4 q4 = *(const float4*)(rp);
        q4.x *= scale; q4.y *= scale; q4.z *= scale; q4.w *= scale;
        *(float4*)(sm + A_QS + row * 36 + seg * 4) = q4;
        *(float4*)(sm + A_KS + row * 36 + seg * 4) = *(const float4*)(rp + Cc);
        *(float4*)(sm + A_VS + row * 36 + seg * 4) = *(const float4*)(rp + 2 * Cc);
    }
    for (int idx = tid; idx < 1024; idx += 128)
        *(float4*)(sm + A_AP + idx * 4) = *(const float4*)(aphi + h * 4096 + idx * 4);
    for (int idx = tid; idx < 240; idx += 128) {
        *(float4*)(sm + A_CT + idx * 4) = *(const float4*)(cst_g + win * 960 + idx * 4);
        *(float4*)(sm + A_ST + idx * 4) = *(const float4*)(snt_g + win * 960 + idx * 4);
    }
    if (tid < 15) {
        int rad = tid - 7;
        int ira = rad < 0 ? rad + 15 : rad;
        sm[A_AR + tid] = a_r[ira * 16 + h];
        sm[A_BR + tid] = b_r[ira * 16 + h];
    }
    __syncthreads();

    const int qrow = lane >> 2, l3 = lane & 3;
    const int wrow = warp * 16;
    const int iL = wrow + qrow, iH = iL + 8;

    float acc[8][4];
    #pragma unroll
    for (int nt = 0; nt < 8; nt++)
        #pragma unroll
        for (int q = 0; q < 4; q++) acc[nt][q] = 0.0f;

    float afr[4][4];
    #pragma unroll
    for (int kk = 0; kk < 4; kk++) {
        int c = kk * 8 + l3;
        afr[kk][0] = sm[A_QS + iL * 36 + c];
        afr[kk][1] = sm[A_QS + iH * 36 + c];
        afr[kk][2] = sm[A_QS + iL * 36 + c + 4];
        afr[kk][3] = sm[A_QS + iH * 36 + c + 4];
    }
    #pragma unroll
    for (int nt = 0; nt < 8; nt++) {
        int nrow = nt * 8 + qrow;
        #pragma unroll
        for (int kk = 0; kk < 4; kk++) {
            float b0 = sm[A_KS + nrow * 36 + kk * 8 + l3];
            float b1 = sm[A_KS + nrow * 36 + kk * 8 + l3 + 4];
            mma_tf32_f(acc[nt], afr[kk], b0, b1);
        }
    }

    float mlo = -1e30f, mhi = -1e30f;
    #pragma unroll
    for (int nt = 0; nt < 8; nt++) {
        int irL = 2 * warp - nt + 7;
        int irH = irL + 1;
        int j0 = nt * 8 + 2 * l3;
        float aL = sm[A_AR + irL], bL = sm[A_BR + irL];
        float aH = sm[A_AR + irH], bH = sm[A_BR + irH];
        acc[nt][0] += sm[A_AP + iL * 64 + j0]     + aL * sm[A_CT + irL * 64 + j0]     + bL * sm[A_ST + irL * 64 + j0];
        acc[nt][1] += sm[A_AP + iL * 64 + j0 + 1] + aL * sm[A_CT + irL * 64 + j0 + 1] + bL * sm[A_ST + irL * 64 + j0 + 1];
        acc[nt][2] += sm[A_AP + iH * 64 + j0]     + aH * sm[A_CT + irH * 64 + j0]     + bH * sm[A_ST + irH * 64 + j0];
        acc[nt][3] += sm[A_AP + iH * 64 + j0 + 1] + aH * sm[A_CT + irH * 64 + j0 + 1] + bH * sm[A_ST + irH * 64 + j0 + 1];
        mlo = fmaxf(mlo, fmaxf(acc[nt][0], acc[nt][1]));
        mhi = fmaxf(mhi, fmaxf(acc[nt][2], acc[nt][3]));
    }
    mlo = fmaxf(mlo, __shfl_xor_sync(0xffffffffu, mlo, 1));
    mlo = fmaxf(mlo, __shfl_xor_sync(0xffffffffu, mlo, 2));
    mhi = fmaxf(mhi, __shfl_xor_sync(0xffffffffu, mhi, 1));
    mhi = fmaxf(mhi, __shfl_xor_sync(0xffffffffu, mhi, 2));

    float slo = 0.0f, shi = 0.0f;
    #pragma unroll
    for (int nt = 0; nt < 8; nt++) {
        acc[nt][0] = __expf(acc[nt][0] - mlo);
        acc[nt][1] = __expf(acc[nt][1] - mlo);
        acc[nt][2] = __expf(acc[nt][2] - mhi);
        acc[nt][3] = __expf(acc[nt][3] - mhi);
        slo += acc[nt][0] + acc[nt][1];
        shi += acc[nt][2] + acc[nt][3];
    }
    slo += __shfl_xor_sync(0xffffffffu, slo, 1);
    slo += __shfl_xor_sync(0xffffffffu, slo, 2);
    shi += __shfl_xor_sync(0xffffffffu, shi, 1);
    shi += __shfl_xor_sync(0xffffffffu, shi, 2);
    float invL = 1.0f / slo, invH = 1.0f / shi;

    #pragma unroll
    for (int nt = 0; nt < 8; nt++) {
        int j0 = nt * 8 + 2 * l3;
        float2 plo; plo.x = acc[nt][0]; plo.y = acc[nt][1];
        float2 phi; phi.x = acc[nt][2]; phi.y = acc[nt][3];
        *(float2*)(sm + A_SS + iL * 68 + j0) = plo;
        *(float2*)(sm + A_SS + iH * 68 + j0) = phi;
    }
    __syncwarp();

    float oacc[4][4];
    #pragma unroll
    for (int nt = 0; nt < 4; nt++)
        #pragma unroll
        for (int q = 0; q < 4; q++) oacc[nt][q] = 0.0f;

    #pragma unroll
    for (int kk = 0; kk < 8; kk++) {
        float pa[4];
        int c = kk * 8 + l3;
        pa[0] = sm[A_SS + iL * 68 + c];
        pa[1] = sm[A_SS + iH * 68 + c];
        pa[2] = sm[A_SS + iL * 68 + c + 4];
        pa[3] = sm[A_SS + iH * 68 + c + 4];
        #pragma unroll
        for (int nt = 0; nt < 4; nt++) {
            float b0 = sm[A_VS + (kk * 8 + l3) * 36 + nt * 8 + qrow];
            float b1 = sm[A_VS + (kk * 8 + l3 + 4) * 36 + nt * 8 + qrow];
            mma_tf32_f(oacc[nt], pa, b0, b1);
        }
    }

    #pragma unroll
    for (int nt = 0; nt < 4; nt++) {
        int d0 = nt * 8 + 2 * l3;
        float2 lo; lo.x = oacc[nt][0] * invL; lo.y = oacc[nt][1] * invL;
        float2 hi; hi.x = oacc[nt][2] * invH; hi.y = oacc[nt][3] * invH;
        *(float2*)(ctx + (size_t)(base + iL) * Cc + h * HD + d0) = lo;
        *(float2*)(ctx + (size_t)(base + iH) * Cc + h * HD + d0) = hi;
    }
}

// ---------------- launch ----------------
#define GEMM_SMEM (3 * GSTAGE)

extern "C" void kernel_launch(void* const* d_in, const int* in_sizes, int n_in,
                              void* d_out, int out_size)
{
    const float* x       = (const float*)d_in[0];
    const float* D       = (const float*)d_in[1];
    const float* norm1_g = (const float*)d_in[2];
    const float* norm1_b = (const float*)d_in[3];
    const float* qkv_w   = (const float*)d_in[4];
    const float* qkv_b   = (const float*)d_in[5];
    const float* proj_w  = (const float*)d_in[6];
    const float* proj_b  = (const float*)d_in[7];
    const float* a_p     = (const float*)d_in[8];
    const float* b_p     = (const float*)d_in[9];
    const float* a_r     = (const float*)d_in[10];
    const float* b_r     = (const float*)d_in[11];
    const float* norm2_g = (const float*)d_in[12];
    const float* norm2_b = (const float*)d_in[13];
    const float* fc1_w   = (const float*)d_in[14];
    const float* fc1_b   = (const float*)d_in[15];
    const float* fc2_w   = (const float*)d_in[16];
    const float* fc2_b   = (const float*)d_in[17];
    float* out = (float*)d_out;

    float *p_xw, *p_dw, *p_qkv, *p_ctx, *p_x2, *p_xn2, *p_h, *p_aphi, *p_cst, *p_snt;
    cudaGetSymbolAddress((void**)&p_xw,   g_xw);
    cudaGetSymbolAddress((void**)&p_dw,   g_dw);
    cudaGetSymbolAddress((void**)&p_qkv,  g_qkv);
    cudaGetSymbolAddress((void**)&p_ctx,  g_ctx);
    cudaGetSymbolAddress((void**)&p_x2,   g_x2);
    cudaGetSymbolAddress((void**)&p_xn2,  g_xn2);
    cudaGetSymbolAddress((void**)&p_h,    g_h);
    cudaGetSymbolAddress((void**)&p_aphi, g_aphi);
    cudaGetSymbolAddress((void**)&p_cst,  g_cst);
    cudaGetSymbolAddress((void**)&p_snt,  g_snt);

    cudaFuncSetAttribute(gemm_mma<0>, cudaFuncAttributeMaxDynamicSharedMemorySize, GEMM_SMEM);
    cudaFuncSetAttribute(gemm_mma<1>, cudaFuncAttributeMaxDynamicSharedMemorySize, GEMM_SMEM);
    cudaFuncSetAttribute(gemm_mma<2>, cudaFuncAttributeMaxDynamicSharedMemorySize, GEMM_SMEM);
    cudaFuncSetAttribute(gemm_mma<3>, cudaFuncAttributeMaxDynamicSharedMemorySize, GEMM_SMEM);
    cudaFuncSetAttribute(attn_mma, cudaFuncAttributeMaxDynamicSharedMemorySize, ATTN_SMEM);

    // 1. azimuth bias table
    aphi_kernel<<<(NHh * Nn * Nn + 255) / 256, 256>>>(a_p, b_p);

    // 2. LN1 + window partition
    ln_kernel<true><<<MROWS, 128>>>(x, norm1_g, norm1_b, D, p_xw, p_dw);

    // 3. radial sincos tables
    rtab_kernel<<<(NWIN * 15 * 64 + 255) / 256, 256>>>(p_dw);

    // 4. QKV GEMM
    gemm_mma<0><<<dim3(3 * Cc / 128, MROWS / 128), 128, GEMM_SMEM>>>(
        p_xw, qkv_w, qkv_b, nullptr, p_qkv, MROWS, 3 * Cc, Cc);

    // 5. attention (tensor core)
    attn_mma<<<NWIN * NHh, 128, ATTN_SMEM>>>(p_qkv, p_aphi, p_cst, p_snt, a_r, b_r, p_ctx);

    // 6. proj GEMM + window reverse + residual
    gemm_mma<1><<<dim3(Cc / 128, MROWS / 128), 128, GEMM_SMEM>>>(
        p_ctx, proj_w, proj_b, x, p_x2, MROWS, Cc, Cc);

    // 7. LN2
    ln_kernel<false><<<MROWS, 128>>>(p_x2, norm2_g, norm2_b, nullptr, p_xn2, nullptr);

    // 8. fc1 + GELU
    gemm_mma<2><<<dim3(HID / 128, MROWS / 128), 128, GEMM_SMEM>>>(
        p_xn2, fc1_w, fc1_b, nullptr, p_h, MROWS, HID, Cc);

    // 9. fc2 + residual -> out
    gemm_mma<3><<<dim3(Cc / 128, MROWS / 128), 128, GEMM_SMEM>>>(
        p_h, fc2_w, fc2_b, p_x2, out, MROWS, Cc, HID);
}

// round 10
// speedup vs baseline: 4.8217x; 1.1183x over previous
#include <cuda_runtime.h>
#include <cuda_bf16.h>
#include <cstdint>

// ---------------- problem constants ----------------
#define B_    16
#define Hh    64
#define WRES  64
#define Cc    512
#define NHh   16
#define Nn    64
#define HD    32
#define HID   2048
#define NWIN  1024
#define MROWS 65536
#define PI_F  3.14159265358979323846f

// ---------------- scratch ----------------
__device__ float g_xw [MROWS * Cc];
__device__ float g_dw [MROWS];
__device__ float g_qkv[MROWS * 3 * Cc];
__device__ float g_ctx[MROWS * Cc];
__device__ float g_x2 [MROWS * Cc];
__device__ float g_xn2[MROWS * Cc];
__device__ float g_h  [MROWS * HID];
__device__ float g_aphi[NHh * Nn * Nn];
__device__ float g_cst[NWIN * 15 * 64];
__device__ float g_snt[NWIN * 15 * 64];

// ---------------- helpers ----------------
__device__ __forceinline__ uint32_t smem_u32(const void* p) {
    uint32_t a;
    asm("{ .reg .u64 t; cvta.to.shared.u64 t, %1; cvt.u32.u64 %0, t; }" : "=r"(a) : "l"(p));
    return a;
}
__device__ __forceinline__ void cp_async16(uint32_t saddr, const void* gaddr) {
    asm volatile("cp.async.cg.shared.global [%0], [%1], 16;" :: "r"(saddr), "l"(gaddr) : "memory");
}
__device__ __forceinline__ void cp_commit() {
    asm volatile("cp.async.commit_group;" ::: "memory");
}
template<int NN>
__device__ __forceinline__ void cp_wait() {
    asm volatile("cp.async.wait_group %0;" :: "n"(NN) : "memory");
}
__device__ __forceinline__ void ldmatrix4(uint32_t* r, uint32_t addr) {
    asm volatile("ldmatrix.sync.aligned.m8n8.x4.shared.b16 {%0,%1,%2,%3}, [%4];"
        : "=r"(r[0]), "=r"(r[1]), "=r"(r[2]), "=r"(r[3]) : "r"(addr));
}
__device__ __forceinline__ void mma_tf32(float* c, const uint32_t* a, const uint32_t* b) {
    asm volatile(
        "mma.sync.aligned.m16n8k8.row.col.f32.tf32.tf32.f32 "
        "{%0,%1,%2,%3}, {%4,%5,%6,%7}, {%8,%9}, {%0,%1,%2,%3};"
        : "+f"(c[0]), "+f"(c[1]), "+f"(c[2]), "+f"(c[3])
        : "r"(a[0]), "r"(a[1]), "r"(a[2]), "r"(a[3]), "r"(b[0]), "r"(b[1]));
}
__device__ __forceinline__ void mma_tf32_f(float* c, const float* a, float b0, float b1) {
    asm volatile(
        "mma.sync.aligned.m16n8k8.row.col.f32.tf32.tf32.f32 "
        "{%0,%1,%2,%3}, {%4,%5,%6,%7}, {%8,%9}, {%0,%1,%2,%3};"
        : "+f"(c[0]), "+f"(c[1]), "+f"(c[2]), "+f"(c[3])
        : "r"(__float_as_uint(a[0])), "r"(__float_as_uint(a[1])),
          "r"(__float_as_uint(a[2])), "r"(__float_as_uint(a[3])),
          "r"(__float_as_uint(b0)), "r"(__float_as_uint(b1)));
}

// ---------------- A_phi precompute ----------------
__global__ void aphi_kernel(const float* __restrict__ a_p, const float* __restrict__ b_p)
{
    int idx = blockIdx.x * blockDim.x + threadIdx.x;
    if (idx >= NHh * Nn * Nn) return;
    int h = idx >> 12;
    int rem = idx & 4095;
    int i = rem >> 6, j = rem & 63;
    int az = (i & 7) - (j & 7);
    int ip = az < 0 ? az + 15 : az;
    float azf = (float)az * (2.0f * PI_F / (float)WRES);
    g_aphi[idx] = a_p[ip * NHh + h] * cosf(azf) + b_p[ip * NHh + h] * sinf(azf);
}

// ---------------- radial sincos tables: [win][rad+7][j] ----------------
__global__ void rtab_kernel(const float* __restrict__ dw)
{
    int idx = blockIdx.x * blockDim.x + threadIdx.x;
    if (idx >= NWIN * 15 * 64) return;
    int win = idx / 960;
    int rem = idx - win * 960;
    int ir = rem >> 6;
    int j = rem & 63;
    float ang = (float)(ir - 7) * dw[win * 64 + j] * (2.0f * PI_F / 256.0f);
    float sn, cs;
    sincosf(ang, &sn, &cs);
    g_cst[idx] = cs;
    g_snt[idx] = sn;
}

// ---------------- LayerNorm (+ optional window partition) ----------------
template<bool PERM>
__launch_bounds__(128)
__global__ void ln_kernel(const float* __restrict__ x, const float* __restrict__ g,
                          const float* __restrict__ b, const float* __restrict__ D,
                          float* __restrict__ out, float* __restrict__ dwout)
{
    int r = blockIdx.x;
    int tid = threadIdx.x;
    float4 v = ((const float4*)(x + (size_t)r * Cc))[tid];
    float s = v.x + v.y + v.z + v.w;
    float sq = v.x * v.x + v.y * v.y + v.z * v.z + v.w * v.w;
    #pragma unroll
    for (int o = 16; o; o >>= 1) {
        s += __shfl_xor_sync(0xffffffffu, s, o);
        sq += __shfl_xor_sync(0xffffffffu, sq, o);
    }
    __shared__ float ss[4], sqs[4];
    int w = tid >> 5;
    if ((tid & 31) == 0) { ss[w] = s; sqs[w] = sq; }
    __syncthreads();
    s = ss[0] + ss[1] + ss[2] + ss[3];
    sq = sqs[0] + sqs[1] + sqs[2] + sqs[3];
    float mean = s * (1.0f / Cc);
    float var = sq * (1.0f / Cc) - mean * mean;
    float rstd = rsqrtf(var + 1e-5f);
    float4 gg = ((const float4*)g)[tid];
    float4 bb = ((const float4*)b)[tid];
    float4 o;
    o.x = (v.x - mean) * rstd * gg.x + bb.x;
    o.y = (v.y - mean) * rstd * gg.y + bb.y;
    o.z = (v.z - mean) * rstd * gg.z + bb.z;
    o.w = (v.w - mean) * rstd * gg.w + bb.w;
    int dst = r;
    if (PERM) {
        int bI = r >> 12;
        int hh = (r >> 6) & 63;
        int wc = r & 63;
        int win = bI * 64 + (hh >> 3) * 8 + (wc >> 3);
        int rin = (hh & 7) * 8 + (wc & 7);
        dst = win * 64 + rin;
        if (tid == 0) dwout[dst] = D[r];
    }
    ((float4*)(out + (size_t)dst * Cc))[tid] = o;
}

// ============ tf32 mma.sync GEMM: Y = A(MxK) @ W^T (W NNxKK) + bias ============
// Tile BM=128, BN=128, BK=32. 3-stage cp.async pipeline, one barrier/iter.
// 4 warps (128 threads), warp tile 64x64; register-lean (compile-time N,K).
// 2 CTAs/SM. MODE 0: plain  1: window-reverse+residual  2: GELU  3: residual
#define GSTAGE 32768
template<int MODE, int NN, int KK>
__launch_bounds__(128, 2)
__global__ void gemm_mma(const float* __restrict__ A, const float* __restrict__ W,
                         const float* __restrict__ bias, const float* __restrict__ res,
                         float* __restrict__ out)
{
    extern __shared__ char smem[];
    const uint32_t sbase = smem_u32(smem);   // stage s: A (16KB) then B (16KB)
    const int tid = threadIdx.x;
    const int bm = blockIdx.y * 128;
    const int bn = blockIdx.x * 128;
    const int warp = tid >> 5, lane = tid & 31;

    // ---- per-thread prefetch constants ----
    const int row0 = tid >> 3;               // 0..15
    const int seg  = tid & 7;
    const uint32_t so_base = (uint32_t)(row0 * 128 + ((seg ^ (row0 & 7)) << 4));
    const float* pA = A + (size_t)(bm + row0) * KK + seg * 4;
    const float* pB = W + (size_t)(bn + row0) * KK + seg * 4;

    // ---- per-thread fragment addressing constants ----
    const int wm = warp & 1, wn = warp >> 1;
    const int arow = wm * 64 + ((lane >> 3) & 1) * 8 + (lane & 7);
    const uint32_t abase = (uint32_t)(arow * 128);
    const uint32_t ax7   = (uint32_t)((arow & 7) << 4);
    const uint32_t al16  = (uint32_t)((lane >> 4) * 16);
    const int brow = wn * 64 + ((lane >> 4) & 1) * 8 + (lane & 7);
    const uint32_t bbase = (uint32_t)(brow * 128) + 16384u;
    const uint32_t bx7   = (uint32_t)((brow & 7) << 4);
    const uint32_t bl16  = (uint32_t)(((lane >> 3) & 1) * 16);

    float acc[4][8][4];
    #pragma unroll
    for (int i = 0; i < 4; i++)
        #pragma unroll
        for (int j = 0; j < 8; j++)
            #pragma unroll
            for (int q = 0; q < 4; q++) acc[i][j][q] = 0.0f;

    const int nk = KK >> 5;

    auto prefetch = [&](int kt, int stage) {
        uint32_t ab = sbase + (uint32_t)stage * GSTAGE + so_base;
        const float* a_src = pA + kt * 32;
        const float* b_src = pB + kt * 32;
        #pragma unroll
        for (int t = 0; t < 8; t++) {
            cp_async16(ab + (uint32_t)(t * 2048),          a_src + t * 16 * KK);
            cp_async16(ab + (uint32_t)(t * 2048) + 16384u, b_src + t * 16 * KK);
        }
    };

    prefetch(0, 0); cp_commit();
    prefetch(1, 1); cp_commit();

    for (int kt = 0; kt < nk; kt++) {
        cp_wait<1>();
        __syncthreads();
        if (kt + 2 < nk) {
            prefetch(kt + 2, (kt + 2) % 3);
        }
        cp_commit();

        uint32_t sb = sbase + (uint32_t)(kt % 3) * GSTAGE;

        #pragma unroll
        for (int ks = 0; ks < 4; ks++) {
            const uint32_t aoff = ((uint32_t)(ks * 32) + al16) ^ ax7;
            const uint32_t boff = ((uint32_t)(ks * 32) + bl16) ^ bx7;
            uint32_t af[4][4];
            #pragma unroll
            for (int am = 0; am < 4; am++)
                ldmatrix4(af[am], sb + abase + (uint32_t)(am * 2048) + aoff);
            #pragma unroll
            for (int bp = 0; bp < 4; bp++) {
                uint32_t r[4];
                ldmatrix4(r, sb + bbase + (uint32_t)(bp * 2048) + boff);
                #pragma unroll
                for (int am = 0; am < 4; am++) {
                    mma_tf32(acc[am][bp * 2 + 0], af[am], r);
                    mma_tf32(acc[am][bp * 2 + 1], af[am], r + 2);
                }
            }
        }
    }

    // ---------------- epilogue ----------------
    #pragma unroll
    for (int am = 0; am < 4; am++) {
        #pragma unroll
        for (int half = 0; half < 2; half++) {
            int m = bm + wm * 64 + am * 16 + half * 8 + (lane >> 2);
            uint32_t obase;
            if (MODE == 1) {
                int win = m >> 6, rin = m & 63;
                int bI = win >> 6, wb = (win >> 3) & 7, wwi = win & 7;
                int hh = wb * 8 + (rin >> 3);
                int wc = wwi * 8 + (rin & 7);
                obase = (uint32_t)(bI * (Hh * WRES) + hh * 64 + wc) * NN;
            } else {
                obase = (uint32_t)m * NN;
            }
            #pragma unroll
            for (int an = 0; an < 8; an++) {
                int n = bn + wn * 64 + an * 8 + (lane & 3) * 2;
                float2 bv = *(const float2*)(bias + n);
                float x0 = acc[am][an][half * 2 + 0] + bv.x;
                float x1 = acc[am][an][half * 2 + 1] + bv.y;
                if (MODE == 2) {
                    x0 = 0.5f * x0 * (1.0f + erff(x0 * 0.70710678118654752f));
                    x1 = 0.5f * x1 * (1.0f + erff(x1 * 0.70710678118654752f));
                }
                if (MODE == 1 || MODE == 3) {
                    float2 rv = *(const float2*)(res + obase + n);
                    x0 += rv.x; x1 += rv.y;
                }
                float2 o; o.x = x0; o.y = x1;
                *(float2*)(out + obase + n) = o;
            }
        }
    }
}

// ============ tensor-core attention per (window, head) ============
#define A_QS 0
#define A_KS 2304
#define A_VS 4608
#define A_SS 6912      /* 64 x 68 */
#define A_AP 11264     /* 4096 */
#define A_CT 15360     /* 960 */
#define A_ST 16320     /* 960 */
#define A_AR 17280     /* 16 */
#define A_BR 17296     /* 16 */
#define ATTN_SMEM (17312 * 4)

__launch_bounds__(128)
__global__ void attn_mma(const float* __restrict__ qkv,
                         const float* __restrict__ aphi,
                         const float* __restrict__ cst_g, const float* __restrict__ snt_g,
                         const float* __restrict__ a_r, const float* __restrict__ b_r,
                         float* __restrict__ ctx)
{
    extern __shared__ float sm[];
    int win = blockIdx.x >> 4;
    int h = blockIdx.x & 15;
    int tid = threadIdx.x;
    int warp = tid >> 5, lane = tid & 31;
    int base = win * 64;
    const float scale = 0.17677669529663687f;

    for (int idx = tid; idx < 512; idx += 128) {
        int row = idx >> 3, seg = idx & 7;
        const float* rp = qkv + (size_t)(base + row) * (3 * Cc) + h * HD + seg * 4;
        float4 q4 = *(const float4*)(rp);
        q4.x *= scale; q4.y *= scale; q4.z *= scale; q4.w *= scale;
        *(float4*)(sm + A_QS + row * 36 + seg * 4) = q4;
        *(float4*)(sm + A_KS + row * 36 + seg * 4) = *(const float4*)(rp + Cc);
        *(float4*)(sm + A_VS + row * 36 + seg * 4) = *(const float4*)(rp + 2 * Cc);
    }
    for (int idx = tid; idx < 1024; idx += 128)
        *(float4*)(sm + A_AP + idx * 4) = *(const float4*)(aphi + h * 4096 + idx * 4);
    for (int idx = tid; idx < 240; idx += 128) {
        *(float4*)(sm + A_CT + idx * 4) = *(const float4*)(cst_g + win * 960 + idx * 4);
        *(float4*)(sm + A_ST + idx * 4) = *(const float4*)(snt_g + win * 960 + idx * 4);
    }
    if (tid < 15) {
        int rad = tid - 7;
        int ira = rad < 0 ? rad + 15 : rad;
        sm[A_AR + tid] = a_r[ira * 16 + h];
        sm[A_BR + tid] = b_r[ira * 16 + h];
    }
    __syncthreads();

    const int qrow = lane >> 2, l3 = lane & 3;
    const int wrow = warp * 16;
    const int iL = wrow + qrow, iH = iL + 8;

    float acc[8][4];
    #pragma unroll
    for (int nt = 0; nt < 8; nt++)
        #pragma unroll
        for (int q = 0; q < 4; q++) acc[nt][q] = 0.0f;

    float afr[4][4];
    #pragma unroll
    for (int kk = 0; kk < 4; kk++) {
        int c = kk * 8 + l3;
        afr[kk][0] = sm[A_QS + iL * 36 + c];
        afr[kk][1] = sm[A_QS + iH * 36 + c];
        afr[kk][2] = sm[A_QS + iL * 36 + c + 4];
        afr[kk][3] = sm[A_QS + iH * 36 + c + 4];
    }
    #pragma unroll
    for (int nt = 0; nt < 8; nt++) {
        int nrow = nt * 8 + qrow;
        #pragma unroll
        for (int kk = 0; kk < 4; kk++) {
            float b0 = sm[A_KS + nrow * 36 + kk * 8 + l3];
            float b1 = sm[A_KS + nrow * 36 + kk * 8 + l3 + 4];
            mma_tf32_f(acc[nt], afr[kk], b0, b1);
        }
    }

    float mlo = -1e30f, mhi = -1e30f;
    #pragma unroll
    for (int nt = 0; nt < 8; nt++) {
        int irL = 2 * warp - nt + 7;
        int irH = irL + 1;
        int j0 = nt * 8 + 2 * l3;
        float aL = sm[A_AR + irL], bL = sm[A_BR + irL];
        float aH = sm[A_AR + irH], bH = sm[A_BR + irH];
        acc[nt][0] += sm[A_AP + iL * 64 + j0]     + aL * sm[A_CT + irL * 64 + j0]     + bL * sm[A_ST + irL * 64 + j0];
        acc[nt][1] += sm[A_AP + iL * 64 + j0 + 1] + aL * sm[A_CT + irL * 64 + j0 + 1] + bL * sm[A_ST + irL * 64 + j0 + 1];
        acc[nt][2] += sm[A_AP + iH * 64 + j0]     + aH * sm[A_CT + irH * 64 + j0]     + bH * sm[A_ST + irH * 64 + j0];
        acc[nt][3] += sm[A_AP + iH * 64 + j0 + 1] + aH * sm[A_CT + irH * 64 + j0 + 1] + bH * sm[A_ST + irH * 64 + j0 + 1];
        mlo = fmaxf(mlo, fmaxf(acc[nt][0], acc[nt][1]));
        mhi = fmaxf(mhi, fmaxf(acc[nt][2], acc[nt][3]));
    }
    mlo = fmaxf(mlo, __shfl_xor_sync(0xffffffffu, mlo, 1));
    mlo = fmaxf(mlo, __shfl_xor_sync(0xffffffffu, mlo, 2));
    mhi = fmaxf(mhi, __shfl_xor_sync(0xffffffffu, mhi, 1));
    mhi = fmaxf(mhi, __shfl_xor_sync(0xffffffffu, mhi, 2));

    float slo = 0.0f, shi = 0.0f;
    #pragma unroll
    for (int nt = 0; nt < 8; nt++) {
        acc[nt][0] = __expf(acc[nt][0] - mlo);
        acc[nt][1] = __expf(acc[nt][1] - mlo);
        acc[nt][2] = __expf(acc[nt][2] - mhi);
        acc[nt][3] = __expf(acc[nt][3] - mhi);
        slo += acc[nt][0] + acc[nt][1];
        shi += acc[nt][2] + acc[nt][3];
    }
    slo += __shfl_xor_sync(0xffffffffu, slo, 1);
    slo += __shfl_xor_sync(0xffffffffu, slo, 2);
    shi += __shfl_xor_sync(0xffffffffu, shi, 1);
    shi += __shfl_xor_sync(0xffffffffu, shi, 2);
    float invL = 1.0f / slo, invH = 1.0f / shi;

    #pragma unroll
    for (int nt = 0; nt < 8; nt++) {
        int j0 = nt * 8 + 2 * l3;
        float2 plo; plo.x = acc[nt][0]; plo.y = acc[nt][1];
        float2 phi; phi.x = acc[nt][2]; phi.y = acc[nt][3];
        *(float2*)(sm + A_SS + iL * 68 + j0) = plo;
        *(float2*)(sm + A_SS + iH * 68 + j0) = phi;
    }
    __syncwarp();

    float oacc[4][4];
    #pragma unroll
    for (int nt = 0; nt < 4; nt++)
        #pragma unroll
        for (int q = 0; q < 4; q++) oacc[nt][q] = 0.0f;

    #pragma unroll
    for (int kk = 0; kk < 8; kk++) {
        float pa[4];
        int c = kk * 8 + l3;
        pa[0] = sm[A_SS + iL * 68 + c];
        pa[1] = sm[A_SS + iH * 68 + c];
        pa[2] = sm[A_SS + iL * 68 + c + 4];
        pa[3] = sm[A_SS + iH * 68 + c + 4];
        #pragma unroll
        for (int nt = 0; nt < 4; nt++) {
            float b0 = sm[A_VS + (kk * 8 + l3) * 36 + nt * 8 + qrow];
            float b1 = sm[A_VS + (kk * 8 + l3 + 4) * 36 + nt * 8 + qrow];
            mma_tf32_f(oacc[nt], pa, b0, b1);
        }
    }

    #pragma unroll
    for (int nt = 0; nt < 4; nt++) {
        int d0 = nt * 8 + 2 * l3;
        float2 lo; lo.x = oacc[nt][0] * invL; lo.y = oacc[nt][1] * invL;
        float2 hi; hi.x = oacc[nt][2] * invH; hi.y = oacc[nt][3] * invH;
        *(float2*)(ctx + (size_t)(base + iL) * Cc + h * HD + d0) = lo;
        *(float2*)(ctx + (size_t)(base + iH) * Cc + h * HD + d0) = hi;
    }
}

// ---------------- launch ----------------
#define GEMM_SMEM (3 * GSTAGE)

extern "C" void kernel_launch(void* const* d_in, const int* in_sizes, int n_in,
                              void* d_out, int out_size)
{
    const float* x       = (const float*)d_in[0];
    const float* D       = (const float*)d_in[1];
    const float* norm1_g = (const float*)d_in[2];
    const float* norm1_b = (const float*)d_in[3];
    const float* qkv_w   = (const float*)d_in[4];
    const float* qkv_b   = (const float*)d_in[5];
    const float* proj_w  = (const float*)d_in[6];
    const float* proj_b  = (const float*)d_in[7];
    const float* a_p     = (const float*)d_in[8];
    const float* b_p     = (const float*)d_in[9];
    const float* a_r     = (const float*)d_in[10];
    const float* b_r     = (const float*)d_in[11];
    const float* norm2_g = (const float*)d_in[12];
    const float* norm2_b = (const float*)d_in[13];
    const float* fc1_w   = (const float*)d_in[14];
    const float* fc1_b   = (const float*)d_in[15];
    const float* fc2_w   = (const float*)d_in[16];
    const float* fc2_b   = (const float*)d_in[17];
    float* out = (float*)d_out;

    float *p_xw, *p_dw, *p_qkv, *p_ctx, *p_x2, *p_xn2, *p_h, *p_aphi, *p_cst, *p_snt;
    cudaGetSymbolAddress((void**)&p_xw,   g_xw);
    cudaGetSymbolAddress((void**)&p_dw,   g_dw);
    cudaGetSymbolAddress((void**)&p_qkv,  g_qkv);
    cudaGetSymbolAddress((void**)&p_ctx,  g_ctx);
    cudaGetSymbolAddress((void**)&p_x2,   g_x2);
    cudaGetSymbolAddress((void**)&p_xn2,  g_xn2);
    cudaGetSymbolAddress((void**)&p_h,    g_h);
    cudaGetSymbolAddress((void**)&p_aphi, g_aphi);
    cudaGetSymbolAddress((void**)&p_cst,  g_cst);
    cudaGetSymbolAddress((void**)&p_snt,  g_snt);

    cudaFuncSetAttribute((gemm_mma<0, 1536, 512>),  cudaFuncAttributeMaxDynamicSharedMemorySize, GEMM_SMEM);
    cudaFuncSetAttribute((gemm_mma<1, 512, 512>),   cudaFuncAttributeMaxDynamicSharedMemorySize, GEMM_SMEM);
    cudaFuncSetAttribute((gemm_mma<2, 2048, 512>),  cudaFuncAttributeMaxDynamicSharedMemorySize, GEMM_SMEM);
    cudaFuncSetAttribute((gemm_mma<3, 512, 2048>),  cudaFuncAttributeMaxDynamicSharedMemorySize, GEMM_SMEM);
    cudaFuncSetAttribute(attn_mma, cudaFuncAttributeMaxDynamicSharedMemorySize, ATTN_SMEM);

    // 1. azimuth bias table
    aphi_kernel<<<(NHh * Nn * Nn + 255) / 256, 256>>>(a_p, b_p);

    // 2. LN1 + window partition
    ln_kernel<true><<<MROWS, 128>>>(x, norm1_g, norm1_b, D, p_xw, p_dw);

    // 3. radial sincos tables
    rtab_kernel<<<(NWIN * 15 * 64 + 255) / 256, 256>>>(p_dw);

    // 4. QKV GEMM
    gemm_mma<0, 1536, 512><<<dim3(1536 / 128, MROWS / 128), 128, GEMM_SMEM>>>(
        p_xw, qkv_w, qkv_b, nullptr, p_qkv);

    // 5. attention (tensor core)
    attn_mma<<<NWIN * NHh, 128, ATTN_SMEM>>>(p_qkv, p_aphi, p_cst, p_snt, a_r, b_r, p_ctx);

    // 6. proj GEMM + window reverse + residual
    gemm_mma<1, 512, 512><<<dim3(512 / 128, MROWS / 128), 128, GEMM_SMEM>>>(
        p_ctx, proj_w, proj_b, x, p_x2);

    // 7. LN2
    ln_kernel<false><<<MROWS, 128>>>(p_x2, norm2_g, norm2_b, nullptr, p_xn2, nullptr);

    // 8. fc1 + GELU
    gemm_mma<2, 2048, 512><<<dim3(2048 / 128, MROWS / 128), 128, GEMM_SMEM>>>(
        p_xn2, fc1_w, fc1_b, nullptr, p_h);

    // 9. fc2 + residual -> out
    gemm_mma<3, 512, 2048><<<dim3(512 / 128, MROWS / 128), 128, GEMM_SMEM>>>(
        p_h, fc2_w, fc2_b, p_x2, out);
}

// round 12
// speedup vs baseline: 4.8394x; 1.0037x over previous
#include <cuda_runtime.h>
#include <cuda_bf16.h>
#include <cstdint>

// ---------------- problem constants ----------------
#define B_    16
#define Hh    64
#define WRES  64
#define Cc    512
#define NHh   16
#define Nn    64
#define HD    32
#define HID   2048
#define NWIN  1024
#define MROWS 65536
#define PI_F  3.14159265358979323846f

// ---------------- scratch ----------------
__device__ float g_xw [MROWS * Cc];
__device__ float g_dw [MROWS];
__device__ float g_qkv[MROWS * 3 * Cc];
__device__ float g_ctx[MROWS * Cc];
__device__ float g_x2 [MROWS * Cc];
__device__ float g_xn2[MROWS * Cc];
__device__ float g_h  [MROWS * HID];
__device__ float g_aphi[NHh * Nn * Nn];
__device__ float g_cst[NWIN * 15 * 64];
__device__ float g_snt[NWIN * 15 * 64];

// ---------------- helpers ----------------
__device__ __forceinline__ uint32_t smem_u32(const void* p) {
    uint32_t a;
    asm("{ .reg .u64 t; cvta.to.shared.u64 t, %1; cvt.u32.u64 %0, t; }" : "=r"(a) : "l"(p));
    return a;
}
__device__ __forceinline__ void cp_async16(uint32_t saddr, const void* gaddr) {
    asm volatile("cp.async.cg.shared.global [%0], [%1], 16;" :: "r"(saddr), "l"(gaddr) : "memory");
}
__device__ __forceinline__ void cp_commit() {
    asm volatile("cp.async.commit_group;" ::: "memory");
}
template<int NN>
__device__ __forceinline__ void cp_wait() {
    asm volatile("cp.async.wait_group %0;" :: "n"(NN) : "memory");
}
__device__ __forceinline__ void ldmatrix4(uint32_t* r, uint32_t addr) {
    asm volatile("ldmatrix.sync.aligned.m8n8.x4.shared.b16 {%0,%1,%2,%3}, [%4];"
        : "=r"(r[0]), "=r"(r[1]), "=r"(r[2]), "=r"(r[3]) : "r"(addr));
}
__device__ __forceinline__ void mma_tf32(float* c, const uint32_t* a, const uint32_t* b) {
    asm volatile(
        "mma.sync.aligned.m16n8k8.row.col.f32.tf32.tf32.f32 "
        "{%0,%1,%2,%3}, {%4,%5,%6,%7}, {%8,%9}, {%0,%1,%2,%3};"
        : "+f"(c[0]), "+f"(c[1]), "+f"(c[2]), "+f"(c[3])
        : "r"(a[0]), "r"(a[1]), "r"(a[2]), "r"(a[3]), "r"(b[0]), "r"(b[1]));
}
__device__ __forceinline__ void mma_tf32_f(float* c, const float* a, float b0, float b1) {
    asm volatile(
        "mma.sync.aligned.m16n8k8.row.col.f32.tf32.tf32.f32 "
        "{%0,%1,%2,%3}, {%4,%5,%6,%7}, {%8,%9}, {%0,%1,%2,%3};"
        : "+f"(c[0]), "+f"(c[1]), "+f"(c[2]), "+f"(c[3])
        : "r"(__float_as_uint(a[0])), "r"(__float_as_uint(a[1])),
          "r"(__float_as_uint(a[2])), "r"(__float_as_uint(a[3])),
          "r"(__float_as_uint(b0)), "r"(__float_as_uint(b1)));
}

// ---------------- A_phi precompute ----------------
__global__ void aphi_kernel(const float* __restrict__ a_p, const float* __restrict__ b_p)
{
    int idx = blockIdx.x * blockDim.x + threadIdx.x;
    if (idx >= NHh * Nn * Nn) return;
    int h = idx >> 12;
    int rem = idx & 4095;
    int i = rem >> 6, j = rem & 63;
    int az = (i & 7) - (j & 7);
    int ip = az < 0 ? az + 15 : az;
    float azf = (float)az * (2.0f * PI_F / (float)WRES);
    g_aphi[idx] = a_p[ip * NHh + h] * cosf(azf) + b_p[ip * NHh + h] * sinf(azf);
}

// ---------------- radial sincos tables: [win][rad+7][j] ----------------
__global__ void rtab_kernel(const float* __restrict__ dw)
{
    int idx = blockIdx.x * blockDim.x + threadIdx.x;
    if (idx >= NWIN * 15 * 64) return;
    int win = idx / 960;
    int rem = idx - win * 960;
    int ir = rem >> 6;
    int j = rem & 63;
    float ang = (float)(ir - 7) * dw[win * 64 + j] * (2.0f * PI_F / 256.0f);
    float sn, cs;
    sincosf(ang, &sn, &cs);
    g_cst[idx] = cs;
    g_snt[idx] = sn;
}

// ---------------- LayerNorm (+ optional window partition) ----------------
template<bool PERM>
__launch_bounds__(128)
__global__ void ln_kernel(const float* __restrict__ x, const float* __restrict__ g,
                          const float* __restrict__ b, const float* __restrict__ D,
                          float* __restrict__ out, float* __restrict__ dwout)
{
    int r = blockIdx.x;
    int tid = threadIdx.x;
    float4 v = ((const float4*)(x + (size_t)r * Cc))[tid];
    float s = v.x + v.y + v.z + v.w;
    float sq = v.x * v.x + v.y * v.y + v.z * v.z + v.w * v.w;
    #pragma unroll
    for (int o = 16; o; o >>= 1) {
        s += __shfl_xor_sync(0xffffffffu, s, o);
        sq += __shfl_xor_sync(0xffffffffu, sq, o);
    }
    __shared__ float ss[4], sqs[4];
    int w = tid >> 5;
    if ((tid & 31) == 0) { ss[w] = s; sqs[w] = sq; }
    __syncthreads();
    s = ss[0] + ss[1] + ss[2] + ss[3];
    sq = sqs[0] + sqs[1] + sqs[2] + sqs[3];
    float mean = s * (1.0f / Cc);
    float var = sq * (1.0f / Cc) - mean * mean;
    float rstd = rsqrtf(var + 1e-5f);
    float4 gg = ((const float4*)g)[tid];
    float4 bb = ((const float4*)b)[tid];
    float4 o;
    o.x = (v.x - mean) * rstd * gg.x + bb.x;
    o.y = (v.y - mean) * rstd * gg.y + bb.y;
    o.z = (v.z - mean) * rstd * gg.z + bb.z;
    o.w = (v.w - mean) * rstd * gg.w + bb.w;
    int dst = r;
    if (PERM) {
        int bI = r >> 12;
        int hh = (r >> 6) & 63;
        int wc = r & 63;
        int win = bI * 64 + (hh >> 3) * 8 + (wc >> 3);
        int rin = (hh & 7) * 8 + (wc & 7);
        dst = win * 64 + rin;
        if (tid == 0) dwout[dst] = D[r];
    }
    ((float4*)(out + (size_t)dst * Cc))[tid] = o;
}

// ============ tf32 mma.sync GEMM: Y = A(MxK) @ W^T (W NNxKK) + bias ============
// Tile BM=128, BN=128, BK=32. 3-stage cp.async pipeline, one barrier/iter.
// 4 warps (128 threads), warp tile 64x64. Batched fragment loads per ks (MLP=8).
// 2 CTAs/SM. MODE 0: plain  1: window-reverse+residual  2: GELU  3: residual
#define GSTAGE 32768
template<int MODE, int NN, int KK>
__launch_bounds__(128, 2)
__global__ void gemm_mma(const float* __restrict__ A, const float* __restrict__ W,
                         const float* __restrict__ bias, const float* __restrict__ res,
                         float* __restrict__ out)
{
    extern __shared__ char smem[];
    const uint32_t sbase = smem_u32(smem);   // stage s: A (16KB) then B (16KB)
    const int tid = threadIdx.x;
    const int bm = blockIdx.y * 128;
    const int bn = blockIdx.x * 128;
    const int warp = tid >> 5, lane = tid & 31;

    // ---- per-thread prefetch constants ----
    const int row0 = tid >> 3;               // 0..15
    const int seg  = tid & 7;
    const uint32_t so_base = (uint32_t)(row0 * 128 + ((seg ^ (row0 & 7)) << 4));
    const float* pA = A + (size_t)(bm + row0) * KK + seg * 4;
    const float* pB = W + (size_t)(bn + row0) * KK + seg * 4;

    // ---- per-thread fragment addressing constants ----
    const int wm = warp & 1, wn = warp >> 1;
    const int arow = wm * 64 + ((lane >> 3) & 1) * 8 + (lane & 7);
    const uint32_t abase = (uint32_t)(arow * 128);
    const uint32_t ax7   = (uint32_t)((arow & 7) << 4);
    const uint32_t al16  = (uint32_t)((lane >> 4) * 16);
    const int brow = wn * 64 + ((lane >> 4) & 1) * 8 + (lane & 7);
    const uint32_t bbase = (uint32_t)(brow * 128) + 16384u;
    const uint32_t bx7   = (uint32_t)((brow & 7) << 4);
    const uint32_t bl16  = (uint32_t)(((lane >> 3) & 1) * 16);

    float acc[4][8][4];
    #pragma unroll
    for (int i = 0; i < 4; i++)
        #pragma unroll
        for (int j = 0; j < 8; j++)
            #pragma unroll
            for (int q = 0; q < 4; q++) acc[i][j][q] = 0.0f;

    const int nk = KK >> 5;

    auto prefetch = [&](int kt, int stage) {
        uint32_t ab = sbase + (uint32_t)stage * GSTAGE + so_base;
        const float* a_src = pA + kt * 32;
        const float* b_src = pB + kt * 32;
        #pragma unroll
        for (int t = 0; t < 8; t++) {
            cp_async16(ab + (uint32_t)(t * 2048),          a_src + t * 16 * KK);
            cp_async16(ab + (uint32_t)(t * 2048) + 16384u, b_src + t * 16 * KK);
        }
    };

    prefetch(0, 0); cp_commit();
    prefetch(1, 1); cp_commit();

    for (int kt = 0; kt < nk; kt++) {
        cp_wait<1>();
        __syncthreads();
        if (kt + 2 < nk) {
            prefetch(kt + 2, (kt + 2) % 3);
        }
        cp_commit();

        uint32_t sb = sbase + (uint32_t)(kt % 3) * GSTAGE;

        #pragma unroll
        for (int ks = 0; ks < 4; ks++) {
            const uint32_t aoff = ((uint32_t)(ks * 32) + al16) ^ ax7;
            const uint32_t boff = ((uint32_t)(ks * 32) + bl16) ^ bx7;
            // batch all 8 fragment loads up front (one latency exposure, MLP=8)
            uint32_t af[4][4];
            uint32_t bf[4][4];
            #pragma unroll
            for (int am = 0; am < 4; am++)
                ldmatrix4(af[am], sb + abase + (uint32_t)(am * 2048) + aoff);
            #pragma unroll
            for (int bp = 0; bp < 4; bp++)
                ldmatrix4(bf[bp], sb + bbase + (uint32_t)(bp * 2048) + boff);
            // dependency-free MMA burst
            #pragma unroll
            for (int bp = 0; bp < 4; bp++)
                #pragma unroll
                for (int am = 0; am < 4; am++) {
                    mma_tf32(acc[am][bp * 2 + 0], af[am], bf[bp]);
                    mma_tf32(acc[am][bp * 2 + 1], af[am], bf[bp] + 2);
                }
        }
    }

    // ---------------- epilogue ----------------
    #pragma unroll
    for (int am = 0; am < 4; am++) {
        #pragma unroll
        for (int half = 0; half < 2; half++) {
            int m = bm + wm * 64 + am * 16 + half * 8 + (lane >> 2);
            uint32_t obase;
            if (MODE == 1) {
                int win = m >> 6, rin = m & 63;
                int bI = win >> 6, wb = (win >> 3) & 7, wwi = win & 7;
                int hh = wb * 8 + (rin >> 3);
                int wc = wwi * 8 + (rin & 7);
                obase = (uint32_t)(bI * (Hh * WRES) + hh * 64 + wc) * NN;
            } else {
                obase = (uint32_t)m * NN;
            }
            #pragma unroll
            for (int an = 0; an < 8; an++) {
                int n = bn + wn * 64 + an * 8 + (lane & 3) * 2;
                float2 bv = *(const float2*)(bias + n);
                float x0 = acc[am][an][half * 2 + 0] + bv.x;
                float x1 = acc[am][an][half * 2 + 1] + bv.y;
                if (MODE == 2) {
                    x0 = 0.5f * x0 * (1.0f + erff(x0 * 0.70710678118654752f));
                    x1 = 0.5f * x1 * (1.0f + erff(x1 * 0.70710678118654752f));
                }
                if (MODE == 1 || MODE == 3) {
                    float2 rv = *(const float2*)(res + obase + n);
                    x0 += rv.x; x1 += rv.y;
                }
                float2 o; o.x = x0; o.y = x1;
                *(float2*)(out + obase + n) = o;
            }
        }
    }
}

// ============ tensor-core attention per (window, head) ============
#define A_QS 0
#define A_KS 2304
#define A_VS 4608
#define A_SS 6912      /* 64 x 68 */
#define A_AP 11264     /* 4096 */
#define A_CT 15360     /* 960 */
#define A_ST 16320     /* 960 */
#define A_AR 17280     /* 16 */
#define A_BR 17296     /* 16 */
#define ATTN_SMEM (17312 * 4)

__launch_bounds__(128)
__global__ void attn_mma(const float* __restrict__ qkv,
                         const float* __restrict__ aphi,
                         const float* __restrict__ cst_g, const float* __restrict__ snt_g,
                         const float* __restrict__ a_r, const float* __restrict__ b_r,
                         float* __restrict__ ctx)
{
    extern __shared__ float sm[];
    int win = blockIdx.x >> 4;
    int h = blockIdx.x & 15;
    int tid = threadIdx.x;
    int warp = tid >> 5, lane = tid & 31;
    int base = win * 64;
    const float scale = 0.17677669529663687f;

    for (int idx = tid; idx < 512; idx += 128) {
        int row = idx >> 3, seg = idx & 7;
        const float* rp = qkv + (size_t)(base + row) * (3 * Cc) + h * HD + seg * 4;
        float4 q4 = *(const float4*)(rp);
        q4.x *= scale; q4.y *= scale; q4.z *= scale; q4.w *= scale;
        *(float4*)(sm + A_QS + row * 36 + seg * 4) = q4;
        *(float4*)(sm + A_KS + row * 36 + seg * 4) = *(const float4*)(rp + Cc);
        *(float4*)(sm + A_VS + row * 36 + seg * 4) = *(const float4*)(rp + 2 * Cc);
    }
    for (int idx = tid; idx < 1024; idx += 128)
        *(float4*)(sm + A_AP + idx * 4) = *(const float4*)(aphi + h * 4096 + idx * 4);
    for (int idx = tid; idx < 240; idx += 128) {
        *(float4*)(sm + A_CT + idx * 4) = *(const float4*)(cst_g + win * 960 + idx * 4);
        *(float4*)(sm + A_ST + idx * 4) = *(const float4*)(snt_g + win * 960 + idx * 4);
    }
    if (tid < 15) {
        int rad = tid - 7;
        int ira = rad < 0 ? rad + 15 : rad;
        sm[A_AR + tid] = a_r[ira * 16 + h];
        sm[A_BR + tid] = b_r[ira * 16 + h];
    }
    __syncthreads();

    const int qrow = lane >> 2, l3 = lane & 3;
    const int wrow = warp * 16;
    const int iL = wrow + qrow, iH = iL + 8;

    float acc[8][4];
    #pragma unroll
    for (int nt = 0; nt < 8; nt++)
        #pragma unroll
        for (int q = 0; q < 4; q++) acc[nt][q] = 0.0f;

    float afr[4][4];
    #pragma unroll
    for (int kk = 0; kk < 4; kk++) {
        int c = kk * 8 + l3;
        afr[kk][0] = sm[A_QS + iL * 36 + c];
        afr[kk][1] = sm[A_QS + iH * 36 + c];
        afr[kk][2] = sm[A_QS + iL * 36 + c + 4];
        afr[kk][3] = sm[A_QS + iH * 36 + c + 4];
    }
    #pragma unroll
    for (int nt = 0; nt < 8; nt++) {
        int nrow = nt * 8 + qrow;
        #pragma unroll
        for (int kk = 0; kk < 4; kk++) {
            float b0 = sm[A_KS + nrow * 36 + kk * 8 + l3];
            float b1 = sm[A_KS + nrow * 36 + kk * 8 + l3 + 4];
            mma_tf32_f(acc[nt], afr[kk], b0, b1);
        }
    }

    float mlo = -1e30f, mhi = -1e30f;
    #pragma unroll
    for (int nt = 0; nt < 8; nt++) {
        int irL = 2 * warp - nt + 7;
        int irH = irL + 1;
        int j0 = nt * 8 + 2 * l3;
        float aL = sm[A_AR + irL], bL = sm[A_BR + irL];
        float aH = sm[A_AR + irH], bH = sm[A_BR + irH];
        acc[nt][0] += sm[A_AP + iL * 64 + j0]     + aL * sm[A_CT + irL * 64 + j0]     + bL * sm[A_ST + irL * 64 + j0];
        acc[nt][1] += sm[A_AP + iL * 64 + j0 + 1] + aL * sm[A_CT + irL * 64 + j0 + 1] + bL * sm[A_ST + irL * 64 + j0 + 1];
        acc[nt][2] += sm[A_AP + iH * 64 + j0]     + aH * sm[A_CT + irH * 64 + j0]     + bH * sm[A_ST + irH * 64 + j0];
        acc[nt][3] += sm[A_AP + iH * 64 + j0 + 1] + aH * sm[A_CT + irH * 64 + j0 + 1] + bH * sm[A_ST + irH * 64 + j0 + 1];
        mlo = fmaxf(mlo, fmaxf(acc[nt][0], acc[nt][1]));
        mhi = fmaxf(mhi, fmaxf(acc[nt][2], acc[nt][3]));
    }
    mlo = fmaxf(mlo, __shfl_xor_sync(0xffffffffu, mlo, 1));
    mlo = fmaxf(mlo, __shfl_xor_sync(0xffffffffu, mlo, 2));
    mhi = fmaxf(mhi, __shfl_xor_sync(0xffffffffu, mhi, 1));
    mhi = fmaxf(mhi, __shfl_xor_sync(0xffffffffu, mhi, 2));

    float slo = 0.0f, shi = 0.0f;
    #pragma unroll
    for (int nt = 0; nt < 8; nt++) {
        acc[nt][0] = __expf(acc[nt][0] - mlo);
        acc[nt][1] = __expf(acc[nt][1] - mlo);
        acc[nt][2] = __expf(acc[nt][2] - mhi);
        acc[nt][3] = __expf(acc[nt][3] - mhi);
        slo += acc[nt][0] + acc[nt][1];
        shi += acc[nt][2] + acc[nt][3];
    }
    slo += __shfl_xor_sync(0xffffffffu, slo, 1);
    slo += __shfl_xor_sync(0xffffffffu, slo, 2);
    shi += __shfl_xor_sync(0xffffffffu, shi, 1);
    shi += __shfl_xor_sync(0xffffffffu, shi, 2);
    float invL = 1.0f / slo, invH = 1.0f / shi;

    #pragma unroll
    for (int nt = 0; nt < 8; nt++) {
        int j0 = nt * 8 + 2 * l3;
        float2 plo; plo.x = acc[nt][0]; plo.y = acc[nt][1];
        float2 phi; phi.x = acc[nt][2]; phi.y = acc[nt][3];
        *(float2*)(sm + A_SS + iL * 68 + j0) = plo;
        *(float2*)(sm + A_SS + iH * 68 + j0) = phi;
    }
    __syncwarp();

    float oacc[4][4];
    #pragma unroll
    for (int nt = 0; nt < 4; nt++)
        #pragma unroll
        for (int q = 0; q < 4; q++) oacc[nt][q] = 0.0f;

    #pragma unroll
    for (int kk = 0; kk < 8; kk++) {
        float pa[4];
        int c = kk * 8 + l3;
        pa[0] = sm[A_SS + iL * 68 + c];
        pa[1] = sm[A_SS + iH * 68 + c];
        pa[2] = sm[A_SS + iL * 68 + c + 4];
        pa[3] = sm[A_SS + iH * 68 + c + 4];
        #pragma unroll
        for (int nt = 0; nt < 4; nt++) {
            float b0 = sm[A_VS + (kk * 8 + l3) * 36 + nt * 8 + qrow];
            float b1 = sm[A_VS + (kk * 8 + l3 + 4) * 36 + nt * 8 + qrow];
            mma_tf32_f(oacc[nt], pa, b0, b1);
        }
    }

    #pragma unroll
    for (int nt = 0; nt < 4; nt++) {
        int d0 = nt * 8 + 2 * l3;
        float2 lo; lo.x = oacc[nt][0] * invL; lo.y = oacc[nt][1] * invL;
        float2 hi; hi.x = oacc[nt][2] * invH; hi.y = oacc[nt][3] * invH;
        *(float2*)(ctx + (size_t)(base + iL) * Cc + h * HD + d0) = lo;
        *(float2*)(ctx + (size_t)(base + iH) * Cc + h * HD + d0) = hi;
    }
}

// ---------------- launch ----------------
#define GEMM_SMEM (3 * GSTAGE)

extern "C" void kernel_launch(void* const* d_in, const int* in_sizes, int n_in,
                              void* d_out, int out_size)
{
    const float* x       = (const float*)d_in[0];
    const float* D       = (const float*)d_in[1];
    const float* norm1_g = (const float*)d_in[2];
    const float* norm1_b = (const float*)d_in[3];
    const float* qkv_w   = (const float*)d_in[4];
    const float* qkv_b   = (const float*)d_in[5];
    const float* proj_w  = (const float*)d_in[6];
    const float* proj_b  = (const float*)d_in[7];
    const float* a_p     = (const float*)d_in[8];
    const float* b_p     = (const float*)d_in[9];
    const float* a_r     = (const float*)d_in[10];
    const float* b_r     = (const float*)d_in[11];
    const float* norm2_g = (const float*)d_in[12];
    const float* norm2_b = (const float*)d_in[13];
    const float* fc1_w   = (const float*)d_in[14];
    const float* fc1_b   = (const float*)d_in[15];
    const float* fc2_w   = (const float*)d_in[16];
    const float* fc2_b   = (const float*)d_in[17];
    float* out = (float*)d_out;

    float *p_xw, *p_dw, *p_qkv, *p_ctx, *p_x2, *p_xn2, *p_h, *p_aphi, *p_cst, *p_snt;
    cudaGetSymbolAddress((void**)&p_xw,   g_xw);
    cudaGetSymbolAddress((void**)&p_dw,   g_dw);
    cudaGetSymbolAddress((void**)&p_qkv,  g_qkv);
    cudaGetSymbolAddress((void**)&p_ctx,  g_ctx);
    cudaGetSymbolAddress((void**)&p_x2,   g_x2);
    cudaGetSymbolAddress((void**)&p_xn2,  g_xn2);
    cudaGetSymbolAddress((void**)&p_h,    g_h);
    cudaGetSymbolAddress((void**)&p_aphi, g_aphi);
    cudaGetSymbolAddress((void**)&p_cst,  g_cst);
    cudaGetSymbolAddress((void**)&p_snt,  g_snt);

    cudaFuncSetAttribute((gemm_mma<0, 1536, 512>),  cudaFuncAttributeMaxDynamicSharedMemorySize, GEMM_SMEM);
    cudaFuncSetAttribute((gemm_mma<1, 512, 512>),   cudaFuncAttributeMaxDynamicSharedMemorySize, GEMM_SMEM);
    cudaFuncSetAttribute((gemm_mma<2, 2048, 512>),  cudaFuncAttributeMaxDynamicSharedMemorySize, GEMM_SMEM);
    cudaFuncSetAttribute((gemm_mma<3, 512, 2048>),  cudaFuncAttributeMaxDynamicSharedMemorySize, GEMM_SMEM);
    cudaFuncSetAttribute(attn_mma, cudaFuncAttributeMaxDynamicSharedMemorySize, ATTN_SMEM);

    // 1. azimuth bias table
    aphi_kernel<<<(NHh * Nn * Nn + 255) / 256, 256>>>(a_p, b_p);

    // 2. LN1 + window partition
    ln_kernel<true><<<MROWS, 128>>>(x, norm1_g, norm1_b, D, p_xw, p_dw);

    // 3. radial sincos tables
    rtab_kernel<<<(NWIN * 15 * 64 + 255) / 256, 256>>>(p_dw);

    // 4. QKV GEMM
    gemm_mma<0, 1536, 512><<<dim3(1536 / 128, MROWS / 128), 128, GEMM_SMEM>>>(
        p_xw, qkv_w, qkv_b, nullptr, p_qkv);

    // 5. attention (tensor core)
    attn_mma<<<NWIN * NHh, 128, ATTN_SMEM>>>(p_qkv, p_aphi, p_cst, p_snt, a_r, b_r, p_ctx);

    // 6. proj GEMM + window reverse + residual
    gemm_mma<1, 512, 512><<<dim3(512 / 128, MROWS / 128), 128, GEMM_SMEM>>>(
        p_ctx, proj_w, proj_b, x, p_x2);

    // 7. LN2
    ln_kernel<false><<<MROWS, 128>>>(p_x2, norm2_g, norm2_b, nullptr, p_xn2, nullptr);

    // 8. fc1 + GELU
    gemm_mma<2, 2048, 512><<<dim3(2048 / 128, MROWS / 128), 128, GEMM_SMEM>>>(
        p_xn2, fc1_w, fc1_b, nullptr, p_h);

    // 9. fc2 + residual -> out
    gemm_mma<3, 512, 2048><<<dim3(512 / 128, MROWS / 128), 128, GEMM_SMEM>>>(
        p_h, fc2_w, fc2_b, p_x2, out);
}